// round 11
// baseline (speedup 1.0000x reference)
#include <cuda_runtime.h>
#include <cuda_bf16.h>
#include <math.h>
#include <stdint.h>

#define NBATCH 8
#define TSEQ   2048
#define CDIM   128
#define SCL    0.08838834764831845f   // 1/sqrt(128)
#define NEGMAX -3.402823466e38f

// -------- scratch (static __device__ per harness rules) --------
__device__ float         g_Qf [(size_t)NBATCH * TSEQ * CDIM]; // fp32 Q (raw)
__device__ float         g_Kf [(size_t)NBATCH * TSEQ * CDIM]; // fp32 K (raw)
__device__ __nv_bfloat16 g_Qb [(size_t)NBATCH * TSEQ * CDIM]; // bf16 Q (pre-scaled)
__device__ __nv_bfloat16 g_Kb [(size_t)NBATCH * TSEQ * CDIM]; // bf16 K
__device__ __nv_bfloat16 g_Wos[128 * 256];                    // Wo split [hi||lo]
__device__ __nv_bfloat16 g_OAs[(size_t)NBATCH * TSEQ * 256];  // attn@V split [hi||lo]

__device__ __forceinline__ uint32_t s2u(const void* p) {
    uint32_t a;
    asm("{ .reg .u64 t; cvta.to.shared.u64 t, %1; cvt.u32.u64 %0, t; }" : "=r"(a) : "l"(p));
    return a;
}
__device__ __forceinline__ uint32_t umx(uint32_t a, uint32_t b) { return a > b ? a : b; }
__device__ __forceinline__ uint32_t umn(uint32_t a, uint32_t b) { return a < b ? a : b; }

__device__ __forceinline__ void mma_bf16(float& c0, float& c1, float& c2, float& c3,
    uint32_t a0, uint32_t a1, uint32_t a2, uint32_t a3, uint32_t b0, uint32_t b1) {
    asm volatile("mma.sync.aligned.m16n8k16.row.col.f32.bf16.bf16.f32 "
        "{%0,%1,%2,%3}, {%4,%5,%6,%7}, {%8,%9}, {%0,%1,%2,%3};"
        : "+f"(c0), "+f"(c1), "+f"(c2), "+f"(c3)
        : "r"(a0), "r"(a1), "r"(a2), "r"(a3), "r"(b0), "r"(b1));
}
#define LDMX4(d, ad) \
    asm volatile("ldmatrix.sync.aligned.m8n8.x4.shared.b16 {%0,%1,%2,%3}, [%4];" \
        : "=r"((d)[0]), "=r"((d)[1]), "=r"((d)[2]), "=r"((d)[3]) : "r"(ad))

// inverse of the order-preserving packed map, rounded DOWN (safe threshold)
__device__ __forceinline__ float unpack_th(uint32_t v) {
    uint32_t b = ((int)v < 0) ? ((v & 0xFFFFF800u) ^ 0x80000000u)
                              : (~v | 0x7FFu);
    return __uint_as_float(b);
}

// float-gated packed top-4 insert (common path: 1 compare)
#define GINS4(r0, r1, r2, r3, th, f, cc) { \
    float _f = (f); \
    if (_f > (th)) { \
        uint32_t mb = __float_as_uint(_f); \
        mb = ((int)mb < 0) ? ~mb : (mb | 0x80000000u); \
        uint32_t x = (mb & 0xFFFFF800u) | (cc); \
        uint32_t tt; \
        tt = umx(r0, x); x = umn(r0, x); r0 = tt; \
        tt = umx(r1, x); x = umn(r1, x); r1 = tt; \
        tt = umx(r2, x); x = umn(r2, x); r2 = tt; \
        r3 = umx(r3, x); \
        th = unpack_th(r3); \
    } }

#define INS6(r0, r1, r2, r3, r4, r5, xx) { uint32_t y = (xx), tt; \
    tt = umx(r0, y); y = umn(r0, y); r0 = tt; \
    tt = umx(r1, y); y = umn(r1, y); r1 = tt; \
    tt = umx(r2, y); y = umn(r2, y); r2 = tt; \
    tt = umx(r3, y); y = umn(r3, y); r3 = tt; \
    tt = umx(r4, y); y = umn(r4, y); r4 = tt; \
    r5 = umx(r5, y); }

#define INS3(vv, cc) do { float _v = (vv); int _c = (cc); \
    if (_v > b2) { \
        if (_v > b1) { \
            if (_v > b0) { b2 = b1; i2 = i1; b1 = b0; i1 = i0; b0 = _v; i0 = _c; } \
            else         { b2 = b1; i2 = i1; b1 = _v; i1 = _c; } \
        } else           { b2 = _v; i2 = _c; } \
    } } while (0)

// ============================================================================
// Prep: split Wo into [hi(128) || lo(128)] bf16 rows.
// ============================================================================
__global__ __launch_bounds__(256) void prep_wo(const float4* __restrict__ Wo)
{
    int local = blockIdx.x * 256 + threadIdx.x;
    float4 v = Wo[local];
    int row = local >> 5, c4 = (local & 31) * 4;
    __nv_bfloat16 h0 = __float2bfloat16_rn(v.x), h1 = __float2bfloat16_rn(v.y);
    __nv_bfloat16 h2 = __float2bfloat16_rn(v.z), h3 = __float2bfloat16_rn(v.w);
    __nv_bfloat162 hp0, hp1, lp0, lp1;
    hp0.x = h0; hp0.y = h1; hp1.x = h2; hp1.y = h3;
    lp0.x = __float2bfloat16_rn(v.x - __bfloat162float(h0));
    lp0.y = __float2bfloat16_rn(v.y - __bfloat162float(h1));
    lp1.x = __float2bfloat16_rn(v.z - __bfloat162float(h2));
    lp1.y = __float2bfloat16_rn(v.w - __bfloat162float(h3));
    __nv_bfloat162* ph = (__nv_bfloat162*)(g_Wos + (size_t)row * 256 + c4);
    ph[0] = hp0; ph[1] = hp1;
    __nv_bfloat162* pl = (__nv_bfloat162*)(g_Wos + (size_t)row * 256 + 128 + c4);
    pl[0] = lp0; pl[1] = lp1;
}

// ============================================================================
// Q/K projection (SIMT fp32, exact): writes fp32 raw + bf16 (Q pre-scaled).
// Must stay fp32-exact: the rescore depends on it (R4 lesson).
// ============================================================================
__global__ __launch_bounds__(256) void proj_split(
    const float* __restrict__ E, const float* __restrict__ Wq, const float* __restrict__ Wk)
{
    extern __shared__ float smf[];
    float* As = smf;
    float* Bs = smf + 128 * 128;
    const int tid = threadIdx.x, tx = tid & 15, ty = tid >> 4;
    const int m0 = blockIdx.x * 128;
    const int isK = blockIdx.y;
    const float* W = isK ? Wk : Wq;
    float*         df = isK ? g_Kf : g_Qf;
    __nv_bfloat16* db = isK ? g_Kb : g_Qb;
    const float bscale = isK ? 1.f : SCL;

    {
        const float4* src = (const float4*)(E + (size_t)m0 * 128);
        #pragma unroll
        for (int i = tid; i < 128 * 32; i += 256) {
            int r = i & 127, cq = i >> 7;
            float4 v = src[(size_t)r * 32 + cq];
            float* d = As + (cq * 4) * 128 + r;
            d[0] = v.x; d[128] = v.y; d[256] = v.z; d[384] = v.w;
        }
        const float4* srcb = (const float4*)W;
        #pragma unroll
        for (int i = tid; i < 128 * 32; i += 256) {
            int r = i & 127, cq = i >> 7;
            float4 v = srcb[(size_t)r * 32 + cq];
            float* d = Bs + (cq * 4) * 128 + r;
            d[0] = v.x; d[128] = v.y; d[256] = v.z; d[384] = v.w;
        }
    }
    __syncthreads();

    float acc[8][8];
    #pragma unroll
    for (int i = 0; i < 8; i++)
        #pragma unroll
        for (int j = 0; j < 8; j++) acc[i][j] = 0.f;

    #pragma unroll 4
    for (int c = 0; c < 128; c++) {
        const float* ac = As + c * 128;
        const float* bc = Bs + c * 128;
        float4 a0 = *(const float4*)(ac + ty * 4);
        float4 a1 = *(const float4*)(ac + 64 + ty * 4);
        float4 b0 = *(const float4*)(bc + tx * 4);
        float4 b1 = *(const float4*)(bc + 64 + tx * 4);
        float a[8] = {a0.x, a0.y, a0.z, a0.w, a1.x, a1.y, a1.z, a1.w};
        float b[8] = {b0.x, b0.y, b0.z, b0.w, b1.x, b1.y, b1.z, b1.w};
        #pragma unroll
        for (int i = 0; i < 8; i++)
            #pragma unroll
            for (int j = 0; j < 8; j++)
                acc[i][j] += a[i] * b[j];
    }

    #pragma unroll
    for (int ih = 0; ih < 2; ih++) {
        #pragma unroll
        for (int i = 0; i < 4; i++) {
            const int row = m0 + ih * 64 + ty * 4 + i;
            #pragma unroll
            for (int jh = 0; jh < 2; jh++) {
                const int col = jh * 64 + tx * 4;
                float a0 = acc[ih * 4 + i][jh * 4 + 0];
                float a1 = acc[ih * 4 + i][jh * 4 + 1];
                float a2 = acc[ih * 4 + i][jh * 4 + 2];
                float a3 = acc[ih * 4 + i][jh * 4 + 3];
                *(float4*)(df + (size_t)row * 128 + col) = make_float4(a0, a1, a2, a3);
                __nv_bfloat162 p01, p23;
                p01.x = __float2bfloat16_rn(a0 * bscale);
                p01.y = __float2bfloat16_rn(a1 * bscale);
                p23.x = __float2bfloat16_rn(a2 * bscale);
                p23.y = __float2bfloat16_rn(a3 * bscale);
                __nv_bfloat162* pb = (__nv_bfloat162*)(db + (size_t)row * 128 + col);
                pb[0] = p01; pb[1] = p23;
            }
        }
    }
}

// ============================================================================
// Exact rescore of 6 candidates for one row (quad-cooperative), top-3+softmax.
// ============================================================================
__device__ __forceinline__ void rescore_row(
    const uint32_t* u6, int n, int row, int c4, int* sidx3, float* swgt3)
{
    const float4* qp = (const float4*)(g_Qf + ((size_t)n * TSEQ + row) * 128) + c4 * 8;
    float4 qv[8];
    #pragma unroll
    for (int p = 0; p < 8; p++) qv[p] = qp[p];
    int ids[6];
    #pragma unroll
    for (int j = 0; j < 6; j++) ids[j] = (int)(u6[j] & 2047u);
    float sc[6];
    #pragma unroll
    for (int j = 0; j < 6; j++) {
        const float4* kp = (const float4*)(g_Kf + ((size_t)n * TSEQ + ids[j]) * 128) + c4 * 8;
        float s = 0.f;
        #pragma unroll
        for (int p = 0; p < 8; p++) {
            float4 kv = kp[p];
            s += qv[p].x * kv.x + qv[p].y * kv.y + qv[p].z * kv.z + qv[p].w * kv.w;
        }
        s += __shfl_xor_sync(0xffffffffu, s, 1);
        s += __shfl_xor_sync(0xffffffffu, s, 2);
        sc[j] = s * SCL;
    }
    float b0 = -INFINITY, b1 = -INFINITY, b2 = -INFINITY;
    int i0 = 0, i1 = 0, i2 = 0;
    #pragma unroll
    for (int j = 0; j < 6; j++) INS3(sc[j], ids[j]);
    if (c4 == 0) {
        float e1 = expf(b1 - b0), e2 = expf(b2 - b0);
        float inv = 1.f / (1.f + e1 + e2);
        sidx3[0] = i0; sidx3[1] = i1; sidx3[2] = i2;
        swgt3[0] = inv; swgt3[1] = e1 * inv; swgt3[2] = e2 * inv;
    }
}

// ============================================================================
// Fused scores + top-k, PIPELINED + PHASE-SPLIT:
// phase A: 8 independent MMA chains (32 accum regs, ldmatrix.x4 B operands)
// phase B: float-gated packed top-4 updates on all 32 values (no branches
//          between MMAs -> tensor pipe stays fed).
// ============================================================================
#define OFQ  0u
#define OFK0 34816u
#define OFK1 69632u
#define OFU6 104448          // 128 rows x 6 u32 = 3072
#define OFSI (104448 + 3072)
#define OFSW (104448 + 3072 + 1536)
#define SMEMS (104448 + 3072 + 1536 + 1536)

__global__ __launch_bounds__(512) void scores_fused(
    const float* __restrict__ E, float* __restrict__ attn)
{
    extern __shared__ __align__(16) char smc[];
    const int tid = threadIdx.x, lane = tid & 31, wid = tid >> 5;
    const int g = lane >> 2, c4 = lane & 3;
    const int half = wid >> 3, wq = wid & 7;
    const int n = blockIdx.y, m0 = blockIdx.x * 128;
    uint32_t* u6   = (uint32_t*)(smc + OFU6);
    int*      sidx = (int*)(smc + OFSI);
    float*    swgt = (float*)(smc + OFSW);

    // ---- load Q tile + K tile 0 ----
    {
        const uint4* gq = (const uint4*)(g_Qb + ((size_t)n * TSEQ + m0) * 128);
        const uint4* gk = (const uint4*)(g_Kb + ((size_t)n * TSEQ) * 128);
        #pragma unroll
        for (int j = 0; j < 4; j++) {
            int i = tid + j * 512;
            int r = i >> 4, c = i & 15;
            *(uint4*)(smc + OFQ  + r * 272 + c * 16) = gq[i];
            *(uint4*)(smc + OFK0 + r * 272 + c * 16) = gk[i];
        }
    }
    __syncthreads();

    // A fragments: rows wq*16.., 8 k-steps
    uint32_t A[8][4];
    {
        uint32_t ab = s2u(smc) + OFQ + (uint32_t)((wq * 16 + (lane & 15)) * 272 + (lane >> 4) * 16);
        #pragma unroll
        for (int ks = 0; ks < 8; ks++) LDMX4(A[ks], ab + ks * 32);
    }

    // ldmatrix.x4 B base: lane l covers tile (l>>3) at row (l&7)
    const uint32_t sbB = s2u(smc) + (uint32_t)((lane & 7) * 272 + (lane >> 3) * 16);

    uint4* az = (uint4*)(attn + ((size_t)n * TSEQ + m0) * TSEQ);
    uint32_t cA0 = 0x00800000u, cA1 = 0x00800000u, cA2 = 0x00800000u, cA3 = 0x00800000u;
    uint32_t cB0 = 0x00800000u, cB1 = 0x00800000u, cB2 = 0x00800000u, cB3 = 0x00800000u;
    float thA = NEGMAX, thB = NEGMAX;

    #pragma unroll 1
    for (int t = 0; t < 16; t++) {
        const uint32_t bufR = (t & 1) ? OFK1 : OFK0;
        const uint32_t bufW = (t & 1) ? OFK0 : OFK1;

        // stage next K tile from global (latency hidden behind MMAs below)
        uint4 st0, st1, st2, st3;
        if (t < 15) {
            const uint4* gk = (const uint4*)(g_Kb + ((size_t)n * TSEQ + (size_t)(t + 1) * 128) * 128);
            st0 = gk[tid]; st1 = gk[tid + 512]; st2 = gk[tid + 1024]; st3 = gk[tid + 1536];
        }

        // overlap: zero-fill 1/16 of this CTA's attention block
        {
            uint4 zz = make_uint4(0, 0, 0, 0);
            #pragma unroll
            for (int j = 0; j < 8; j++) az[t * 4096 + j * 512 + tid] = zz;
        }

        // ---- phase A: 8 independent MMA chains ----
        float acc[32];
        #pragma unroll
        for (int nt = 0; nt < 8; nt++) {
            const int ntg = half * 8 + nt;
            const uint32_t bb = bufR + sbB + (uint32_t)(ntg * 8 * 272);
            uint32_t B0[4], B1[4], B2[4], B3[4];
            LDMX4(B0, bb);        LDMX4(B1, bb + 64);
            LDMX4(B2, bb + 128);  LDMX4(B3, bb + 192);
            float c0 = 0.f, c1 = 0.f, c2 = 0.f, c3 = 0.f;
            mma_bf16(c0, c1, c2, c3, A[0][0], A[0][1], A[0][2], A[0][3], B0[0], B0[1]);
            mma_bf16(c0, c1, c2, c3, A[1][0], A[1][1], A[1][2], A[1][3], B0[2], B0[3]);
            mma_bf16(c0, c1, c2, c3, A[2][0], A[2][1], A[2][2], A[2][3], B1[0], B1[1]);
            mma_bf16(c0, c1, c2, c3, A[3][0], A[3][1], A[3][2], A[3][3], B1[2], B1[3]);
            mma_bf16(c0, c1, c2, c3, A[4][0], A[4][1], A[4][2], A[4][3], B2[0], B2[1]);
            mma_bf16(c0, c1, c2, c3, A[5][0], A[5][1], A[5][2], A[5][3], B2[2], B2[3]);
            mma_bf16(c0, c1, c2, c3, A[6][0], A[6][1], A[6][2], A[6][3], B3[0], B3[1]);
            mma_bf16(c0, c1, c2, c3, A[7][0], A[7][1], A[7][2], A[7][3], B3[2], B3[3]);
            acc[nt * 4 + 0] = c0; acc[nt * 4 + 1] = c1;
            acc[nt * 4 + 2] = c2; acc[nt * 4 + 3] = c3;
        }

        // ---- phase B: float-gated top-4 updates ----
        #pragma unroll
        for (int nt = 0; nt < 8; nt++) {
            uint32_t col = (uint32_t)(t * 128 + (half * 8 + nt) * 8 + 2 * c4);
            GINS4(cA0, cA1, cA2, cA3, thA, acc[nt * 4 + 0], col);
            GINS4(cA0, cA1, cA2, cA3, thA, acc[nt * 4 + 1], col + 1);
            GINS4(cB0, cB1, cB2, cB3, thB, acc[nt * 4 + 2], col);
            GINS4(cB0, cB1, cB2, cB3, thB, acc[nt * 4 + 3], col + 1);
        }

        // commit staged tile to the other buffer
        if (t < 15) {
            int r0 = tid >> 4, c0i = tid & 15;
            *(uint4*)(smc + bufW + r0 * 272 + c0i * 16) = st0;
            int i1 = tid + 512;  *(uint4*)(smc + bufW + (i1 >> 4) * 272 + (i1 & 15) * 16) = st1;
            int i2 = tid + 1024; *(uint4*)(smc + bufW + (i2 >> 4) * 272 + (i2 & 15) * 16) = st2;
            int i3 = tid + 1536; *(uint4*)(smc + bufW + (i3 >> 4) * 272 + (i3 & 15) * 16) = st3;
        }
        __syncthreads();
    }

    // ---- quad merge (cols within half) ----
    uint32_t uA0 = cA0, uA1 = cA1, uA2 = cA2, uA3 = cA3, uA4 = 0, uA5 = 0;
    uint32_t uB0 = cB0, uB1 = cB1, uB2 = cB2, uB3 = cB3, uB4 = 0, uB5 = 0;
    #pragma unroll
    for (int mk = 1; mk <= 2; mk <<= 1) {
        uint32_t o0 = __shfl_xor_sync(0xffffffffu, uA0, mk);
        uint32_t o1 = __shfl_xor_sync(0xffffffffu, uA1, mk);
        uint32_t o2 = __shfl_xor_sync(0xffffffffu, uA2, mk);
        uint32_t o3 = __shfl_xor_sync(0xffffffffu, uA3, mk);
        uint32_t o4 = __shfl_xor_sync(0xffffffffu, uA4, mk);
        uint32_t o5 = __shfl_xor_sync(0xffffffffu, uA5, mk);
        INS6(uA0, uA1, uA2, uA3, uA4, uA5, o0); INS6(uA0, uA1, uA2, uA3, uA4, uA5, o1);
        INS6(uA0, uA1, uA2, uA3, uA4, uA5, o2); INS6(uA0, uA1, uA2, uA3, uA4, uA5, o3);
        INS6(uA0, uA1, uA2, uA3, uA4, uA5, o4); INS6(uA0, uA1, uA2, uA3, uA4, uA5, o5);
        o0 = __shfl_xor_sync(0xffffffffu, uB0, mk);
        o1 = __shfl_xor_sync(0xffffffffu, uB1, mk);
        o2 = __shfl_xor_sync(0xffffffffu, uB2, mk);
        o3 = __shfl_xor_sync(0xffffffffu, uB3, mk);
        o4 = __shfl_xor_sync(0xffffffffu, uB4, mk);
        o5 = __shfl_xor_sync(0xffffffffu, uB5, mk);
        INS6(uB0, uB1, uB2, uB3, uB4, uB5, o0); INS6(uB0, uB1, uB2, uB3, uB4, uB5, o1);
        INS6(uB0, uB1, uB2, uB3, uB4, uB5, o2); INS6(uB0, uB1, uB2, uB3, uB4, uB5, o3);
        INS6(uB0, uB1, uB2, uB3, uB4, uB5, o4); INS6(uB0, uB1, uB2, uB3, uB4, uB5, o5);
    }

    const int rowA = wq * 16 + g, rowB = rowA + 8;
    // cross-half merge via smem
    if (half == 1 && c4 == 0) {
        u6[rowA * 6 + 0] = uA0; u6[rowA * 6 + 1] = uA1; u6[rowA * 6 + 2] = uA2;
        u6[rowA * 6 + 3] = uA3; u6[rowA * 6 + 4] = uA4; u6[rowA * 6 + 5] = uA5;
        u6[rowB * 6 + 0] = uB0; u6[rowB * 6 + 1] = uB1; u6[rowB * 6 + 2] = uB2;
        u6[rowB * 6 + 3] = uB3; u6[rowB * 6 + 4] = uB4; u6[rowB * 6 + 5] = uB5;
    }
    __syncthreads();
    if (half == 0) {
        #pragma unroll
        for (int j = 0; j < 6; j++) { INS6(uA0, uA1, uA2, uA3, uA4, uA5, u6[rowA * 6 + j]); }
        #pragma unroll
        for (int j = 0; j < 6; j++) { INS6(uB0, uB1, uB2, uB3, uB4, uB5, u6[rowB * 6 + j]); }
    }
    __syncthreads();
    if (half == 0 && c4 == 0) {
        u6[rowA * 6 + 0] = uA0; u6[rowA * 6 + 1] = uA1; u6[rowA * 6 + 2] = uA2;
        u6[rowA * 6 + 3] = uA3; u6[rowA * 6 + 4] = uA4; u6[rowA * 6 + 5] = uA5;
        u6[rowB * 6 + 0] = uB0; u6[rowB * 6 + 1] = uB1; u6[rowB * 6 + 2] = uB2;
        u6[rowB * 6 + 3] = uB3; u6[rowB * 6 + 4] = uB4; u6[rowB * 6 + 5] = uB5;
    }
    __syncthreads();

    // ---- exact rescore: 128 quads, one row each ----
    {
        const int row = wid * 8 + g;
        uint32_t cand[6];
        #pragma unroll
        for (int j = 0; j < 6; j++) cand[j] = u6[row * 6 + j];
        rescore_row(cand, n, m0 + row, c4, sidx + row * 3, swgt + row * 3);
    }
    __syncthreads();

    // scatter the 3 weights per row (zeros already written)
    if (tid < 128) {
        float* arow = attn + ((size_t)n * TSEQ + m0 + tid) * TSEQ;
        arow[sidx[tid * 3 + 0]] = swgt[tid * 3 + 0];
        arow[sidx[tid * 3 + 1]] = swgt[tid * 3 + 1];
        arow[sidx[tid * 3 + 2]] = swgt[tid * 3 + 2];
    }

    // attn @ V (V = raw E) -> split-bf16 OA rows
    for (int rr = wid; rr < 128; rr += 16) {
        int j0 = sidx[rr * 3], j1 = sidx[rr * 3 + 1], j2 = sidx[rr * 3 + 2];
        float w0 = swgt[rr * 3], w1 = swgt[rr * 3 + 1], w2 = swgt[rr * 3 + 2];
        float4 p0 = ((const float4*)(E + ((size_t)n * TSEQ + j0) * 128))[lane];
        float4 p1 = ((const float4*)(E + ((size_t)n * TSEQ + j1) * 128))[lane];
        float4 p2 = ((const float4*)(E + ((size_t)n * TSEQ + j2) * 128))[lane];
        float ox = w0 * p0.x + w1 * p1.x + w2 * p2.x;
        float oy = w0 * p0.y + w1 * p1.y + w2 * p2.y;
        float oz = w0 * p0.z + w1 * p1.z + w2 * p2.z;
        float ow = w0 * p0.w + w1 * p1.w + w2 * p2.w;
        __nv_bfloat16 hx = __float2bfloat16_rn(ox), hy = __float2bfloat16_rn(oy);
        __nv_bfloat16 hz = __float2bfloat16_rn(oz), hw = __float2bfloat16_rn(ow);
        __nv_bfloat162 h01, h23, l01, l23;
        h01.x = hx; h01.y = hy; h23.x = hz; h23.y = hw;
        l01.x = __float2bfloat16_rn(ox - __bfloat162float(hx));
        l01.y = __float2bfloat16_rn(oy - __bfloat162float(hy));
        l23.x = __float2bfloat16_rn(oz - __bfloat162float(hz));
        l23.y = __float2bfloat16_rn(ow - __bfloat162float(hw));
        __nv_bfloat16* orow = g_OAs + ((size_t)n * TSEQ + m0 + rr) * 256;
        __nv_bfloat162* ph = (__nv_bfloat162*)(orow + lane * 4);
        ph[0] = h01; ph[1] = h23;
        __nv_bfloat162* pl = (__nv_bfloat162*)(orow + 128 + lane * 4);
        pl[0] = l01; pl[1] = l23;
    }
}

// ============================================================================
// Output projection via 3-term split-bf16 MMA: out = OA @ Wo^T + bo.
// ============================================================================
__global__ __launch_bounds__(256) void gemm_out_mma(
    const float* __restrict__ bo, float* __restrict__ out)
{
    extern __shared__ __align__(16) char smc[];
    const int tid = threadIdx.x, lane = tid & 31, w = tid >> 5;
    const int g = lane >> 2, c4 = lane & 3;
    const int m0 = blockIdx.x * 128;

    const uint4* ga = (const uint4*)(g_OAs + (size_t)m0 * 256);
    const uint4* gb = (const uint4*)g_Wos;
    #pragma unroll
    for (int i = tid; i < 4096; i += 256) { int r = i >> 5, c = i & 31; *(uint4*)(smc + r * 528 + c * 16) = ga[i]; }
    #pragma unroll
    for (int i = tid; i < 4096; i += 256) { int r = i >> 5, c = i & 31; *(uint4*)(smc + 67584 + r * 528 + c * 16) = gb[i]; }
    __syncthreads();

    uint32_t A[16][4];
    uint32_t ab = s2u(smc) + (uint32_t)((w * 16 + (lane & 15)) * 528 + (lane >> 4) * 16);
    #pragma unroll
    for (int ks = 0; ks < 16; ks++) LDMX4(A[ks], ab + ks * 32);

    #pragma unroll
    for (int nt = 0; nt < 16; nt++) {
        float c0 = 0.f, c1 = 0.f, c2 = 0.f, c3 = 0.f;
        const char* br = smc + 67584 + (nt * 8 + g) * 528 + c4 * 4;
        #pragma unroll
        for (int ks = 0; ks < 8; ks++) {   // hiA*hiB + loA*hiB
            uint32_t b0 = *(const uint32_t*)(br + ks * 32);
            uint32_t b1 = *(const uint32_t*)(br + ks * 32 + 16);
            mma_bf16(c0, c1, c2, c3, A[ks][0], A[ks][1], A[ks][2], A[ks][3], b0, b1);
            mma_bf16(c0, c1, c2, c3, A[8 + ks][0], A[8 + ks][1], A[8 + ks][2], A[8 + ks][3], b0, b1);
        }
        #pragma unroll
        for (int ks = 0; ks < 8; ks++) {   // hiA*loB
            uint32_t b0 = *(const uint32_t*)(br + 256 + ks * 32);
            uint32_t b1 = *(const uint32_t*)(br + 256 + ks * 32 + 16);
            mma_bf16(c0, c1, c2, c3, A[ks][0], A[ks][1], A[ks][2], A[ks][3], b0, b1);
        }
        const int rA = m0 + w * 16 + g, col = nt * 8 + 2 * c4;
        float bb0 = bo[col], bb1 = bo[col + 1];
        *(float2*)(out + (size_t)rA * 128 + col)       = make_float2(c0 + bb0, c1 + bb1);
        *(float2*)(out + (size_t)(rA + 8) * 128 + col) = make_float2(c2 + bb0, c3 + bb1);
    }
}

// ============================================================================
extern "C" void kernel_launch(void* const* d_in, const int* in_sizes, int n_in,
                              void* d_out, int out_size)
{
    const float* E  = (const float*)d_in[0];
    const float* Wq = (const float*)d_in[2];
    const float* Wk = (const float*)d_in[3];
    const float* Wo = (const float*)d_in[4];
    const float* bo = (const float*)d_in[5];

    float* out  = (float*)d_out;                       // [8,2048,128]
    float* attn = out + (size_t)NBATCH * TSEQ * CDIM;  // [8,1,2048,2048]

    const int SMEM_G = 128 * 128 * 2 * sizeof(float);  // 131072 (proj)
    const int SMEM_P = 2 * 128 * 528;                  // 135168 (out GEMM)
    cudaFuncSetAttribute(proj_split,   cudaFuncAttributeMaxDynamicSharedMemorySize, SMEM_G);
    cudaFuncSetAttribute(gemm_out_mma, cudaFuncAttributeMaxDynamicSharedMemorySize, SMEM_P);
    cudaFuncSetAttribute(scores_fused, cudaFuncAttributeMaxDynamicSharedMemorySize, SMEMS);

    prep_wo<<<16, 256>>>((const float4*)Wo);
    proj_split<<<dim3(128, 2), 256, SMEM_G>>>(E, Wq, Wk);
    scores_fused<<<dim3(16, NBATCH), 512, SMEMS>>>(E, attn);
    gemm_out_mma<<<128, 256, SMEM_P>>>(bo, out);
}

// round 13
// speedup vs baseline: 1.0608x; 1.0608x over previous
#include <cuda_runtime.h>
#include <cuda_bf16.h>
#include <math.h>
#include <stdint.h>

#define NBATCH 8
#define TSEQ   2048
#define CDIM   128
#define SCL    0.08838834764831845f   // 1/sqrt(128)

// -------- scratch (static __device__ per harness rules) --------
__device__ float         g_Qf [(size_t)NBATCH * TSEQ * CDIM]; // fp32 Q (raw)
__device__ float         g_Kf [(size_t)NBATCH * TSEQ * CDIM]; // fp32 K (raw)
__device__ __nv_bfloat16 g_Qb [(size_t)NBATCH * TSEQ * CDIM]; // bf16 Q (pre-scaled)
__device__ __nv_bfloat16 g_Kb [(size_t)NBATCH * TSEQ * CDIM]; // bf16 K
__device__ __nv_bfloat16 g_Wos[128 * 256];                    // Wo split [hi||lo]
__device__ __nv_bfloat16 g_OAs[(size_t)NBATCH * TSEQ * 256];  // attn@V split [hi||lo]

__device__ __forceinline__ uint32_t s2u(const void* p) {
    uint32_t a;
    asm("{ .reg .u64 t; cvta.to.shared.u64 t, %1; cvt.u32.u64 %0, t; }" : "=r"(a) : "l"(p));
    return a;
}
__device__ __forceinline__ uint32_t umx(uint32_t a, uint32_t b) { return a > b ? a : b; }
__device__ __forceinline__ uint32_t umn(uint32_t a, uint32_t b) { return a < b ? a : b; }

__device__ __forceinline__ void mma_bf16(float& c0, float& c1, float& c2, float& c3,
    uint32_t a0, uint32_t a1, uint32_t a2, uint32_t a3, uint32_t b0, uint32_t b1) {
    asm volatile("mma.sync.aligned.m16n8k16.row.col.f32.bf16.bf16.f32 "
        "{%0,%1,%2,%3}, {%4,%5,%6,%7}, {%8,%9}, {%0,%1,%2,%3};"
        : "+f"(c0), "+f"(c1), "+f"(c2), "+f"(c3)
        : "r"(a0), "r"(a1), "r"(a2), "r"(a3), "r"(b0), "r"(b1));
}
#define LDMX4(d, ad) \
    asm volatile("ldmatrix.sync.aligned.m8n8.x4.shared.b16 {%0,%1,%2,%3}, [%4];" \
        : "=r"((d)[0]), "=r"((d)[1]), "=r"((d)[2]), "=r"((d)[3]) : "r"(ad))

// gated packed top-4 chain update (R8 variant — measured best)
#define UPD4(r0, r1, r2, r3, f, cc) { \
    uint32_t mb = __float_as_uint(f); \
    mb = ((int)mb < 0) ? ~mb : (mb | 0x80000000u); \
    uint32_t x = (mb & 0xFFFFF800u) | (cc); \
    if (x > r3) { uint32_t tt; \
        tt = umx(r0, x); x = umn(r0, x); r0 = tt; \
        tt = umx(r1, x); x = umn(r1, x); r1 = tt; \
        tt = umx(r2, x); x = umn(r2, x); r2 = tt; \
        r3 = umx(r3, x); } }

#define INS6(r0, r1, r2, r3, r4, r5, xx) { uint32_t y = (xx), tt; \
    tt = umx(r0, y); y = umn(r0, y); r0 = tt; \
    tt = umx(r1, y); y = umn(r1, y); r1 = tt; \
    tt = umx(r2, y); y = umn(r2, y); r2 = tt; \
    tt = umx(r3, y); y = umn(r3, y); r3 = tt; \
    tt = umx(r4, y); y = umn(r4, y); r4 = tt; \
    r5 = umx(r5, y); }

#define INS3(vv, cc) do { float _v = (vv); int _c = (cc); \
    if (_v > b2) { \
        if (_v > b1) { \
            if (_v > b0) { b2 = b1; i2 = i1; b1 = b0; i1 = i0; b0 = _v; i0 = _c; } \
            else         { b2 = b1; i2 = i1; b1 = _v; i1 = _c; } \
        } else           { b2 = _v; i2 = _c; } \
    } } while (0)

// ============================================================================
// Prep: split Wo into [hi(128) || lo(128)] bf16 rows.
// ============================================================================
__global__ __launch_bounds__(256) void prep_wo(const float4* __restrict__ Wo)
{
    int local = blockIdx.x * 256 + threadIdx.x;
    float4 v = Wo[local];
    int row = local >> 5, c4 = (local & 31) * 4;
    __nv_bfloat16 h0 = __float2bfloat16_rn(v.x), h1 = __float2bfloat16_rn(v.y);
    __nv_bfloat16 h2 = __float2bfloat16_rn(v.z), h3 = __float2bfloat16_rn(v.w);
    __nv_bfloat162 hp0, hp1, lp0, lp1;
    hp0.x = h0; hp0.y = h1; hp1.x = h2; hp1.y = h3;
    lp0.x = __float2bfloat16_rn(v.x - __bfloat162float(h0));
    lp0.y = __float2bfloat16_rn(v.y - __bfloat162float(h1));
    lp1.x = __float2bfloat16_rn(v.z - __bfloat162float(h2));
    lp1.y = __float2bfloat16_rn(v.w - __bfloat162float(h3));
    __nv_bfloat162* ph = (__nv_bfloat162*)(g_Wos + (size_t)row * 256 + c4);
    ph[0] = hp0; ph[1] = hp1;
    __nv_bfloat162* pl = (__nv_bfloat162*)(g_Wos + (size_t)row * 256 + 128 + c4);
    pl[0] = lp0; pl[1] = lp1;
}

// ============================================================================
// Q/K projection (SIMT fp32, exact) + attention zero-fill overlap.
// Proj is FFMA-issue-bound with idle DRAM; the 134 MB zero store drains
// under the compute. Writes fp32 raw + bf16 (Q pre-scaled).
// ============================================================================
__global__ __launch_bounds__(256) void proj_split(
    const float* __restrict__ E, const float* __restrict__ Wq, const float* __restrict__ Wk,
    float* __restrict__ attn)
{
    extern __shared__ float smf[];
    float* As = smf;
    float* Bs = smf + 128 * 128;
    const int tid = threadIdx.x, tx = tid & 15, ty = tid >> 4;
    const int m0 = blockIdx.x * 128;
    const int isK = blockIdx.y;
    const float* W = isK ? Wk : Wq;
    float*         df = isK ? g_Kf : g_Qf;
    __nv_bfloat16* db = isK ? g_Kb : g_Qb;
    const float bscale = isK ? 1.f : SCL;

    {
        const float4* src = (const float4*)(E + (size_t)m0 * 128);
        #pragma unroll
        for (int i = tid; i < 128 * 32; i += 256) {
            int r = i & 127, cq = i >> 7;
            float4 v = src[(size_t)r * 32 + cq];
            float* d = As + (cq * 4) * 128 + r;
            d[0] = v.x; d[128] = v.y; d[256] = v.z; d[384] = v.w;
        }
        const float4* srcb = (const float4*)W;
        #pragma unroll
        for (int i = tid; i < 128 * 32; i += 256) {
            int r = i & 127, cq = i >> 7;
            float4 v = srcb[(size_t)r * 32 + cq];
            float* d = Bs + (cq * 4) * 128 + r;
            d[0] = v.x; d[128] = v.y; d[256] = v.z; d[384] = v.w;
        }
    }

    // ---- attention zero-fill: this CTA covers 1/256 of attn (2 MB) ----
    {
        const int cid = blockIdx.y * 128 + blockIdx.x;
        uint4* az = (uint4*)attn + (size_t)cid * 32768 + tid;
        uint4 zz = make_uint4(0, 0, 0, 0);
        #pragma unroll 8
        for (int j = 0; j < 128; j++) az[j * 256] = zz;
    }
    __syncthreads();

    float acc[8][8];
    #pragma unroll
    for (int i = 0; i < 8; i++)
        #pragma unroll
        for (int j = 0; j < 8; j++) acc[i][j] = 0.f;

    #pragma unroll 4
    for (int c = 0; c < 128; c++) {
        const float* ac = As + c * 128;
        const float* bc = Bs + c * 128;
        float4 a0 = *(const float4*)(ac + ty * 4);
        float4 a1 = *(const float4*)(ac + 64 + ty * 4);
        float4 b0 = *(const float4*)(bc + tx * 4);
        float4 b1 = *(const float4*)(bc + 64 + tx * 4);
        float a[8] = {a0.x, a0.y, a0.z, a0.w, a1.x, a1.y, a1.z, a1.w};
        float b[8] = {b0.x, b0.y, b0.z, b0.w, b1.x, b1.y, b1.z, b1.w};
        #pragma unroll
        for (int i = 0; i < 8; i++)
            #pragma unroll
            for (int j = 0; j < 8; j++)
                acc[i][j] += a[i] * b[j];
    }

    #pragma unroll
    for (int ih = 0; ih < 2; ih++) {
        #pragma unroll
        for (int i = 0; i < 4; i++) {
            const int row = m0 + ih * 64 + ty * 4 + i;
            #pragma unroll
            for (int jh = 0; jh < 2; jh++) {
                const int col = jh * 64 + tx * 4;
                float a0 = acc[ih * 4 + i][jh * 4 + 0];
                float a1 = acc[ih * 4 + i][jh * 4 + 1];
                float a2 = acc[ih * 4 + i][jh * 4 + 2];
                float a3 = acc[ih * 4 + i][jh * 4 + 3];
                *(float4*)(df + (size_t)row * 128 + col) = make_float4(a0, a1, a2, a3);
                __nv_bfloat162 p01, p23;
                p01.x = __float2bfloat16_rn(a0 * bscale);
                p01.y = __float2bfloat16_rn(a1 * bscale);
                p23.x = __float2bfloat16_rn(a2 * bscale);
                p23.y = __float2bfloat16_rn(a3 * bscale);
                __nv_bfloat162* pb = (__nv_bfloat162*)(db + (size_t)row * 128 + col);
                pb[0] = p01; pb[1] = p23;
            }
        }
    }
}

// ============================================================================
// Exact rescore of 6 candidates for one row (quad-cooperative), top-3+softmax.
// ============================================================================
__device__ __forceinline__ void rescore_row(
    const uint32_t* u6, int n, int row, int c4, int* sidx3, float* swgt3)
{
    const float4* qp = (const float4*)(g_Qf + ((size_t)n * TSEQ + row) * 128) + c4 * 8;
    float4 qv[8];
    #pragma unroll
    for (int p = 0; p < 8; p++) qv[p] = qp[p];
    int ids[6];
    #pragma unroll
    for (int j = 0; j < 6; j++) ids[j] = (int)(u6[j] & 2047u);
    float sc[6];
    #pragma unroll
    for (int j = 0; j < 6; j++) {
        const float4* kp = (const float4*)(g_Kf + ((size_t)n * TSEQ + ids[j]) * 128) + c4 * 8;
        float s = 0.f;
        #pragma unroll
        for (int p = 0; p < 8; p++) {
            float4 kv = kp[p];
            s += qv[p].x * kv.x + qv[p].y * kv.y + qv[p].z * kv.z + qv[p].w * kv.w;
        }
        s += __shfl_xor_sync(0xffffffffu, s, 1);
        s += __shfl_xor_sync(0xffffffffu, s, 2);
        sc[j] = s * SCL;
    }
    float b0 = -INFINITY, b1 = -INFINITY, b2 = -INFINITY;
    int i0 = 0, i1 = 0, i2 = 0;
    #pragma unroll
    for (int j = 0; j < 6; j++) INS3(sc[j], ids[j]);
    if (c4 == 0) {
        float e1 = expf(b1 - b0), e2 = expf(b2 - b0);
        float inv = 1.f / (1.f + e1 + e2);
        sidx3[0] = i0; sidx3[1] = i1; sidx3[2] = i2;
        swgt3[0] = inv; swgt3[1] = e1 * inv; swgt3[2] = e2 * inv;
    }
}

// ============================================================================
// Fused scores + top-k, PIPELINED (R8 inner loop, zero-fill removed):
// 512 threads, column-halved warps, double-buffered K with register staging.
// ============================================================================
#define OFQ  0u
#define OFK0 34816u
#define OFK1 69632u
#define OFU6 104448          // 128 rows x 6 u32 = 3072
#define OFSI (104448 + 3072)
#define OFSW (104448 + 3072 + 1536)
#define SMEMS (104448 + 3072 + 1536 + 1536)

__global__ __launch_bounds__(512) void scores_fused(
    const float* __restrict__ E, float* __restrict__ attn)
{
    extern __shared__ __align__(16) char smc[];
    const int tid = threadIdx.x, lane = tid & 31, wid = tid >> 5;
    const int g = lane >> 2, c4 = lane & 3;
    const int half = wid >> 3, wq = wid & 7;
    const int n = blockIdx.y, m0 = blockIdx.x * 128;
    uint32_t* u6   = (uint32_t*)(smc + OFU6);
    int*      sidx = (int*)(smc + OFSI);
    float*    swgt = (float*)(smc + OFSW);

    // ---- load Q tile + K tile 0 ----
    {
        const uint4* gq = (const uint4*)(g_Qb + ((size_t)n * TSEQ + m0) * 128);
        const uint4* gk = (const uint4*)(g_Kb + ((size_t)n * TSEQ) * 128);
        #pragma unroll
        for (int j = 0; j < 4; j++) {
            int i = tid + j * 512;
            int r = i >> 4, c = i & 15;
            *(uint4*)(smc + OFQ  + r * 272 + c * 16) = gq[i];
            *(uint4*)(smc + OFK0 + r * 272 + c * 16) = gk[i];
        }
    }
    __syncthreads();

    // A fragments: rows wq*16.., 8 k-steps
    uint32_t A[8][4];
    {
        uint32_t ab = s2u(smc) + OFQ + (uint32_t)((wq * 16 + (lane & 15)) * 272 + (lane >> 4) * 16);
        #pragma unroll
        for (int ks = 0; ks < 8; ks++) LDMX4(A[ks], ab + ks * 32);
    }

    uint32_t cA0 = 0, cA1 = 0, cA2 = 0, cA3 = 0;
    uint32_t cB0 = 0, cB1 = 0, cB2 = 0, cB3 = 0;

    #pragma unroll 1
    for (int t = 0; t < 16; t++) {
        const uint32_t bufR = (t & 1) ? OFK1 : OFK0;
        const uint32_t bufW = (t & 1) ? OFK0 : OFK1;

        // stage next K tile from global (latency hidden behind MMAs below)
        uint4 st0, st1, st2, st3;
        if (t < 15) {
            const uint4* gk = (const uint4*)(g_Kb + ((size_t)n * TSEQ + (size_t)(t + 1) * 128) * 128);
            st0 = gk[tid]; st1 = gk[tid + 512]; st2 = gk[tid + 1024]; st3 = gk[tid + 1536];
        }

        // MMAs on current buffer: this warp-half's 8 column-tiles
        #pragma unroll
        for (int nt = 0; nt < 8; nt++) {
            const int ntg = half * 8 + nt;
            float c0 = 0.f, c1 = 0.f, c2 = 0.f, c3 = 0.f;
            const char* br = smc + bufR + (ntg * 8 + g) * 272 + c4 * 4;
            #pragma unroll
            for (int ks = 0; ks < 8; ks++) {
                uint32_t b0 = *(const uint32_t*)(br + ks * 32);
                uint32_t b1 = *(const uint32_t*)(br + ks * 32 + 16);
                mma_bf16(c0, c1, c2, c3, A[ks][0], A[ks][1], A[ks][2], A[ks][3], b0, b1);
            }
            uint32_t col = (uint32_t)(t * 128 + ntg * 8 + 2 * c4);
            UPD4(cA0, cA1, cA2, cA3, c0, col);
            UPD4(cA0, cA1, cA2, cA3, c1, col + 1);
            UPD4(cB0, cB1, cB2, cB3, c2, col);
            UPD4(cB0, cB1, cB2, cB3, c3, col + 1);
        }

        // commit staged tile to the other buffer
        if (t < 15) {
            int r0 = tid >> 4, c0i = tid & 15;
            *(uint4*)(smc + bufW + r0 * 272 + c0i * 16) = st0;
            int i1 = tid + 512;  *(uint4*)(smc + bufW + (i1 >> 4) * 272 + (i1 & 15) * 16) = st1;
            int i2 = tid + 1024; *(uint4*)(smc + bufW + (i2 >> 4) * 272 + (i2 & 15) * 16) = st2;
            int i3 = tid + 1536; *(uint4*)(smc + bufW + (i3 >> 4) * 272 + (i3 & 15) * 16) = st3;
        }
        __syncthreads();
    }

    // ---- quad merge (cols within half) ----
    uint32_t uA0 = cA0, uA1 = cA1, uA2 = cA2, uA3 = cA3, uA4 = 0, uA5 = 0;
    uint32_t uB0 = cB0, uB1 = cB1, uB2 = cB2, uB3 = cB3, uB4 = 0, uB5 = 0;
    #pragma unroll
    for (int mk = 1; mk <= 2; mk <<= 1) {
        uint32_t o0 = __shfl_xor_sync(0xffffffffu, uA0, mk);
        uint32_t o1 = __shfl_xor_sync(0xffffffffu, uA1, mk);
        uint32_t o2 = __shfl_xor_sync(0xffffffffu, uA2, mk);
        uint32_t o3 = __shfl_xor_sync(0xffffffffu, uA3, mk);
        uint32_t o4 = __shfl_xor_sync(0xffffffffu, uA4, mk);
        uint32_t o5 = __shfl_xor_sync(0xffffffffu, uA5, mk);
        INS6(uA0, uA1, uA2, uA3, uA4, uA5, o0); INS6(uA0, uA1, uA2, uA3, uA4, uA5, o1);
        INS6(uA0, uA1, uA2, uA3, uA4, uA5, o2); INS6(uA0, uA1, uA2, uA3, uA4, uA5, o3);
        INS6(uA0, uA1, uA2, uA3, uA4, uA5, o4); INS6(uA0, uA1, uA2, uA3, uA4, uA5, o5);
        o0 = __shfl_xor_sync(0xffffffffu, uB0, mk);
        o1 = __shfl_xor_sync(0xffffffffu, uB1, mk);
        o2 = __shfl_xor_sync(0xffffffffu, uB2, mk);
        o3 = __shfl_xor_sync(0xffffffffu, uB3, mk);
        o4 = __shfl_xor_sync(0xffffffffu, uB4, mk);
        o5 = __shfl_xor_sync(0xffffffffu, uB5, mk);
        INS6(uB0, uB1, uB2, uB3, uB4, uB5, o0); INS6(uB0, uB1, uB2, uB3, uB4, uB5, o1);
        INS6(uB0, uB1, uB2, uB3, uB4, uB5, o2); INS6(uB0, uB1, uB2, uB3, uB4, uB5, o3);
        INS6(uB0, uB1, uB2, uB3, uB4, uB5, o4); INS6(uB0, uB1, uB2, uB3, uB4, uB5, o5);
    }

    const int rowA = wq * 16 + g, rowB = rowA + 8;
    // cross-half merge via smem
    if (half == 1 && c4 == 0) {
        u6[rowA * 6 + 0] = uA0; u6[rowA * 6 + 1] = uA1; u6[rowA * 6 + 2] = uA2;
        u6[rowA * 6 + 3] = uA3; u6[rowA * 6 + 4] = uA4; u6[rowA * 6 + 5] = uA5;
        u6[rowB * 6 + 0] = uB0; u6[rowB * 6 + 1] = uB1; u6[rowB * 6 + 2] = uB2;
        u6[rowB * 6 + 3] = uB3; u6[rowB * 6 + 4] = uB4; u6[rowB * 6 + 5] = uB5;
    }
    __syncthreads();
    if (half == 0) {
        #pragma unroll
        for (int j = 0; j < 6; j++) { INS6(uA0, uA1, uA2, uA3, uA4, uA5, u6[rowA * 6 + j]); }
        #pragma unroll
        for (int j = 0; j < 6; j++) { INS6(uB0, uB1, uB2, uB3, uB4, uB5, u6[rowB * 6 + j]); }
    }
    __syncthreads();
    if (half == 0 && c4 == 0) {
        u6[rowA * 6 + 0] = uA0; u6[rowA * 6 + 1] = uA1; u6[rowA * 6 + 2] = uA2;
        u6[rowA * 6 + 3] = uA3; u6[rowA * 6 + 4] = uA4; u6[rowA * 6 + 5] = uA5;
        u6[rowB * 6 + 0] = uB0; u6[rowB * 6 + 1] = uB1; u6[rowB * 6 + 2] = uB2;
        u6[rowB * 6 + 3] = uB3; u6[rowB * 6 + 4] = uB4; u6[rowB * 6 + 5] = uB5;
    }
    __syncthreads();

    // ---- exact rescore: 128 quads, one row each ----
    {
        const int row = wid * 8 + g;
        uint32_t cand[6];
        #pragma unroll
        for (int j = 0; j < 6; j++) cand[j] = u6[row * 6 + j];
        rescore_row(cand, n, m0 + row, c4, sidx + row * 3, swgt + row * 3);
    }
    __syncthreads();

    // scatter the 3 weights per row (zeros already written by proj_split)
    if (tid < 128) {
        float* arow = attn + ((size_t)n * TSEQ + m0 + tid) * TSEQ;
        arow[sidx[tid * 3 + 0]] = swgt[tid * 3 + 0];
        arow[sidx[tid * 3 + 1]] = swgt[tid * 3 + 1];
        arow[sidx[tid * 3 + 2]] = swgt[tid * 3 + 2];
    }

    // attn @ V (V = raw E) -> split-bf16 OA rows
    for (int rr = wid; rr < 128; rr += 16) {
        int j0 = sidx[rr * 3], j1 = sidx[rr * 3 + 1], j2 = sidx[rr * 3 + 2];
        float w0 = swgt[rr * 3], w1 = swgt[rr * 3 + 1], w2 = swgt[rr * 3 + 2];
        float4 p0 = ((const float4*)(E + ((size_t)n * TSEQ + j0) * 128))[lane];
        float4 p1 = ((const float4*)(E + ((size_t)n * TSEQ + j1) * 128))[lane];
        float4 p2 = ((const float4*)(E + ((size_t)n * TSEQ + j2) * 128))[lane];
        float ox = w0 * p0.x + w1 * p1.x + w2 * p2.x;
        float oy = w0 * p0.y + w1 * p1.y + w2 * p2.y;
        float oz = w0 * p0.z + w1 * p1.z + w2 * p2.z;
        float ow = w0 * p0.w + w1 * p1.w + w2 * p2.w;
        __nv_bfloat16 hx = __float2bfloat16_rn(ox), hy = __float2bfloat16_rn(oy);
        __nv_bfloat16 hz = __float2bfloat16_rn(oz), hw = __float2bfloat16_rn(ow);
        __nv_bfloat162 h01, h23, l01, l23;
        h01.x = hx; h01.y = hy; h23.x = hz; h23.y = hw;
        l01.x = __float2bfloat16_rn(ox - __bfloat162float(hx));
        l01.y = __float2bfloat16_rn(oy - __bfloat162float(hy));
        l23.x = __float2bfloat16_rn(oz - __bfloat162float(hz));
        l23.y = __float2bfloat16_rn(ow - __bfloat162float(hw));
        __nv_bfloat16* orow = g_OAs + ((size_t)n * TSEQ + m0 + rr) * 256;
        __nv_bfloat162* ph = (__nv_bfloat162*)(orow + lane * 4);
        ph[0] = h01; ph[1] = h23;
        __nv_bfloat162* pl = (__nv_bfloat162*)(orow + 128 + lane * 4);
        pl[0] = l01; pl[1] = l23;
    }
}

// ============================================================================
// Output projection via 3-term split-bf16 MMA, 4-way nt-interleaved:
// 4 independent accumulator chains break the 24-deep MMA RAW chain.
// ============================================================================
__global__ __launch_bounds__(256) void gemm_out_mma(
    const float* __restrict__ bo, float* __restrict__ out)
{
    extern __shared__ __align__(16) char smc[];
    const int tid = threadIdx.x, lane = tid & 31, w = tid >> 5;
    const int g = lane >> 2, c4 = lane & 3;
    const int m0 = blockIdx.x * 128;

    const uint4* ga = (const uint4*)(g_OAs + (size_t)m0 * 256);
    const uint4* gb = (const uint4*)g_Wos;
    #pragma unroll
    for (int i = tid; i < 4096; i += 256) { int r = i >> 5, c = i & 31; *(uint4*)(smc + r * 528 + c * 16) = ga[i]; }
    #pragma unroll
    for (int i = tid; i < 4096; i += 256) { int r = i >> 5, c = i & 31; *(uint4*)(smc + 67584 + r * 528 + c * 16) = gb[i]; }
    __syncthreads();

    uint32_t A[16][4];
    uint32_t ab = s2u(smc) + (uint32_t)((w * 16 + (lane & 15)) * 528 + (lane >> 4) * 16);
    #pragma unroll
    for (int ks = 0; ks < 16; ks++) LDMX4(A[ks], ab + ks * 32);

    #pragma unroll
    for (int ntg = 0; ntg < 4; ntg++) {
        float acc[4][4];
        #pragma unroll
        for (int j = 0; j < 4; j++)
            #pragma unroll
            for (int q = 0; q < 4; q++) acc[j][q] = 0.f;

        #pragma unroll
        for (int ks = 0; ks < 8; ks++) {
            #pragma unroll
            for (int j = 0; j < 4; j++) {
                const char* br = smc + 67584 + ((ntg * 4 + j) * 8 + g) * 528 + c4 * 4;
                uint32_t b0 = *(const uint32_t*)(br + ks * 32);
                uint32_t b1 = *(const uint32_t*)(br + ks * 32 + 16);
                mma_bf16(acc[j][0], acc[j][1], acc[j][2], acc[j][3],
                         A[ks][0], A[ks][1], A[ks][2], A[ks][3], b0, b1);
                mma_bf16(acc[j][0], acc[j][1], acc[j][2], acc[j][3],
                         A[8 + ks][0], A[8 + ks][1], A[8 + ks][2], A[8 + ks][3], b0, b1);
                uint32_t l0 = *(const uint32_t*)(br + 256 + ks * 32);
                uint32_t l1 = *(const uint32_t*)(br + 256 + ks * 32 + 16);
                mma_bf16(acc[j][0], acc[j][1], acc[j][2], acc[j][3],
                         A[ks][0], A[ks][1], A[ks][2], A[ks][3], l0, l1);
            }
        }

        #pragma unroll
        for (int j = 0; j < 4; j++) {
            const int nt = ntg * 4 + j;
            const int rA = m0 + w * 16 + g, col = nt * 8 + 2 * c4;
            float bb0 = bo[col], bb1 = bo[col + 1];
            *(float2*)(out + (size_t)rA * 128 + col)       = make_float2(acc[j][0] + bb0, acc[j][1] + bb1);
            *(float2*)(out + (size_t)(rA + 8) * 128 + col) = make_float2(acc[j][2] + bb0, acc[j][3] + bb1);
        }
    }
}

// ============================================================================
extern "C" void kernel_launch(void* const* d_in, const int* in_sizes, int n_in,
                              void* d_out, int out_size)
{
    const float* E  = (const float*)d_in[0];
    const float* Wq = (const float*)d_in[2];
    const float* Wk = (const float*)d_in[3];
    const float* Wo = (const float*)d_in[4];
    const float* bo = (const float*)d_in[5];

    float* out  = (float*)d_out;                       // [8,2048,128]
    float* attn = out + (size_t)NBATCH * TSEQ * CDIM;  // [8,1,2048,2048]

    const int SMEM_G = 128 * 128 * 2 * sizeof(float);  // 131072 (proj)
    const int SMEM_P = 2 * 128 * 528;                  // 135168 (out GEMM)
    cudaFuncSetAttribute(proj_split,   cudaFuncAttributeMaxDynamicSharedMemorySize, SMEM_G);
    cudaFuncSetAttribute(gemm_out_mma, cudaFuncAttributeMaxDynamicSharedMemorySize, SMEM_P);
    cudaFuncSetAttribute(scores_fused, cudaFuncAttributeMaxDynamicSharedMemorySize, SMEMS);

    prep_wo<<<16, 256>>>((const float4*)Wo);
    proj_split<<<dim3(128, 2), 256, SMEM_G>>>(E, Wq, Wk, attn);
    scores_fused<<<dim3(16, NBATCH), 512, SMEMS>>>(E, attn);
    gemm_out_mma<<<128, 256, SMEM_P>>>(bo, out);
}

// round 14
// speedup vs baseline: 1.1106x; 1.0469x over previous
#include <cuda_runtime.h>
#include <cuda_bf16.h>
#include <math.h>
#include <stdint.h>

#define NBATCH 8
#define TSEQ   2048
#define CDIM   128
#define SCL    0.08838834764831845f   // 1/sqrt(128)

// -------- scratch (static __device__ per harness rules) --------
__device__ float         g_Qf [(size_t)NBATCH * TSEQ * CDIM]; // fp32 Q (raw)
__device__ float         g_Kf [(size_t)NBATCH * TSEQ * CDIM]; // fp32 K (raw)
__device__ __nv_bfloat16 g_Qb [(size_t)NBATCH * TSEQ * CDIM]; // bf16 Q (pre-scaled)
__device__ __nv_bfloat16 g_Kb [(size_t)NBATCH * TSEQ * CDIM]; // bf16 K
__device__ __nv_bfloat16 g_Wos[128 * 256];                    // Wo split [hi||lo]

__device__ __forceinline__ uint32_t s2u(const void* p) {
    uint32_t a;
    asm("{ .reg .u64 t; cvta.to.shared.u64 t, %1; cvt.u32.u64 %0, t; }" : "=r"(a) : "l"(p));
    return a;
}
__device__ __forceinline__ uint32_t umx(uint32_t a, uint32_t b) { return a > b ? a : b; }
__device__ __forceinline__ uint32_t umn(uint32_t a, uint32_t b) { return a < b ? a : b; }

__device__ __forceinline__ void mma_bf16(float& c0, float& c1, float& c2, float& c3,
    uint32_t a0, uint32_t a1, uint32_t a2, uint32_t a3, uint32_t b0, uint32_t b1) {
    asm volatile("mma.sync.aligned.m16n8k16.row.col.f32.bf16.bf16.f32 "
        "{%0,%1,%2,%3}, {%4,%5,%6,%7}, {%8,%9}, {%0,%1,%2,%3};"
        : "+f"(c0), "+f"(c1), "+f"(c2), "+f"(c3)
        : "r"(a0), "r"(a1), "r"(a2), "r"(a3), "r"(b0), "r"(b1));
}
#define LDMX4(d, ad) \
    asm volatile("ldmatrix.sync.aligned.m8n8.x4.shared.b16 {%0,%1,%2,%3}, [%4];" \
        : "=r"((d)[0]), "=r"((d)[1]), "=r"((d)[2]), "=r"((d)[3]) : "r"(ad))

// gated packed top-4 chain update (R8 variant — measured best)
#define UPD4(r0, r1, r2, r3, f, cc) { \
    uint32_t mb = __float_as_uint(f); \
    mb = ((int)mb < 0) ? ~mb : (mb | 0x80000000u); \
    uint32_t x = (mb & 0xFFFFF800u) | (cc); \
    if (x > r3) { uint32_t tt; \
        tt = umx(r0, x); x = umn(r0, x); r0 = tt; \
        tt = umx(r1, x); x = umn(r1, x); r1 = tt; \
        tt = umx(r2, x); x = umn(r2, x); r2 = tt; \
        r3 = umx(r3, x); } }

#define INS6(r0, r1, r2, r3, r4, r5, xx) { uint32_t y = (xx), tt; \
    tt = umx(r0, y); y = umn(r0, y); r0 = tt; \
    tt = umx(r1, y); y = umn(r1, y); r1 = tt; \
    tt = umx(r2, y); y = umn(r2, y); r2 = tt; \
    tt = umx(r3, y); y = umn(r3, y); r3 = tt; \
    tt = umx(r4, y); y = umn(r4, y); r4 = tt; \
    r5 = umx(r5, y); }

#define INS3(vv, cc) do { float _v = (vv); int _c = (cc); \
    if (_v > b2) { \
        if (_v > b1) { \
            if (_v > b0) { b2 = b1; i2 = i1; b1 = b0; i1 = i0; b0 = _v; i0 = _c; } \
            else         { b2 = b1; i2 = i1; b1 = _v; i1 = _c; } \
        } else           { b2 = _v; i2 = _c; } \
    } } while (0)

// ============================================================================
// Prep: split Wo into [hi(128) || lo(128)] bf16 rows.
// ============================================================================
__global__ __launch_bounds__(256) void prep_wo(const float4* __restrict__ Wo)
{
    int local = blockIdx.x * 256 + threadIdx.x;
    float4 v = Wo[local];
    int row = local >> 5, c4 = (local & 31) * 4;
    __nv_bfloat16 h0 = __float2bfloat16_rn(v.x), h1 = __float2bfloat16_rn(v.y);
    __nv_bfloat16 h2 = __float2bfloat16_rn(v.z), h3 = __float2bfloat16_rn(v.w);
    __nv_bfloat162 hp0, hp1, lp0, lp1;
    hp0.x = h0; hp0.y = h1; hp1.x = h2; hp1.y = h3;
    lp0.x = __float2bfloat16_rn(v.x - __bfloat162float(h0));
    lp0.y = __float2bfloat16_rn(v.y - __bfloat162float(h1));
    lp1.x = __float2bfloat16_rn(v.z - __bfloat162float(h2));
    lp1.y = __float2bfloat16_rn(v.w - __bfloat162float(h3));
    __nv_bfloat162* ph = (__nv_bfloat162*)(g_Wos + (size_t)row * 256 + c4);
    ph[0] = hp0; ph[1] = hp1;
    __nv_bfloat162* pl = (__nv_bfloat162*)(g_Wos + (size_t)row * 256 + 128 + c4);
    pl[0] = lp0; pl[1] = lp1;
}

// ============================================================================
// Q/K projection (SIMT fp32, exact) + attention zero-fill overlap.
// ============================================================================
__global__ __launch_bounds__(256) void proj_split(
    const float* __restrict__ E, const float* __restrict__ Wq, const float* __restrict__ Wk,
    float* __restrict__ attn)
{
    extern __shared__ float smf[];
    float* As = smf;
    float* Bs = smf + 128 * 128;
    const int tid = threadIdx.x, tx = tid & 15, ty = tid >> 4;
    const int m0 = blockIdx.x * 128;
    const int isK = blockIdx.y;
    const float* W = isK ? Wk : Wq;
    float*         df = isK ? g_Kf : g_Qf;
    __nv_bfloat16* db = isK ? g_Kb : g_Qb;
    const float bscale = isK ? 1.f : SCL;

    {
        const float4* src = (const float4*)(E + (size_t)m0 * 128);
        #pragma unroll
        for (int i = tid; i < 128 * 32; i += 256) {
            int r = i & 127, cq = i >> 7;
            float4 v = src[(size_t)r * 32 + cq];
            float* d = As + (cq * 4) * 128 + r;
            d[0] = v.x; d[128] = v.y; d[256] = v.z; d[384] = v.w;
        }
        const float4* srcb = (const float4*)W;
        #pragma unroll
        for (int i = tid; i < 128 * 32; i += 256) {
            int r = i & 127, cq = i >> 7;
            float4 v = srcb[(size_t)r * 32 + cq];
            float* d = Bs + (cq * 4) * 128 + r;
            d[0] = v.x; d[128] = v.y; d[256] = v.z; d[384] = v.w;
        }
    }

    // ---- attention zero-fill: this CTA covers 1/256 of attn (2 MB) ----
    {
        const int cid = blockIdx.y * 128 + blockIdx.x;
        uint4* az = (uint4*)attn + (size_t)cid * 32768 + tid;
        uint4 zz = make_uint4(0, 0, 0, 0);
        #pragma unroll 8
        for (int j = 0; j < 128; j++) az[j * 256] = zz;
    }
    __syncthreads();

    float acc[8][8];
    #pragma unroll
    for (int i = 0; i < 8; i++)
        #pragma unroll
        for (int j = 0; j < 8; j++) acc[i][j] = 0.f;

    #pragma unroll 4
    for (int c = 0; c < 128; c++) {
        const float* ac = As + c * 128;
        const float* bc = Bs + c * 128;
        float4 a0 = *(const float4*)(ac + ty * 4);
        float4 a1 = *(const float4*)(ac + 64 + ty * 4);
        float4 b0 = *(const float4*)(bc + tx * 4);
        float4 b1 = *(const float4*)(bc + 64 + tx * 4);
        float a[8] = {a0.x, a0.y, a0.z, a0.w, a1.x, a1.y, a1.z, a1.w};
        float b[8] = {b0.x, b0.y, b0.z, b0.w, b1.x, b1.y, b1.z, b1.w};
        #pragma unroll
        for (int i = 0; i < 8; i++)
            #pragma unroll
            for (int j = 0; j < 8; j++)
                acc[i][j] += a[i] * b[j];
    }

    #pragma unroll
    for (int ih = 0; ih < 2; ih++) {
        #pragma unroll
        for (int i = 0; i < 4; i++) {
            const int row = m0 + ih * 64 + ty * 4 + i;
            #pragma unroll
            for (int jh = 0; jh < 2; jh++) {
                const int col = jh * 64 + tx * 4;
                float a0 = acc[ih * 4 + i][jh * 4 + 0];
                float a1 = acc[ih * 4 + i][jh * 4 + 1];
                float a2 = acc[ih * 4 + i][jh * 4 + 2];
                float a3 = acc[ih * 4 + i][jh * 4 + 3];
                *(float4*)(df + (size_t)row * 128 + col) = make_float4(a0, a1, a2, a3);
                __nv_bfloat162 p01, p23;
                p01.x = __float2bfloat16_rn(a0 * bscale);
                p01.y = __float2bfloat16_rn(a1 * bscale);
                p23.x = __float2bfloat16_rn(a2 * bscale);
                p23.y = __float2bfloat16_rn(a3 * bscale);
                __nv_bfloat162* pb = (__nv_bfloat162*)(db + (size_t)row * 128 + col);
                pb[0] = p01; pb[1] = p23;
            }
        }
    }
}

// ============================================================================
// Exact rescore of 6 candidates for one row (quad-cooperative), top-3+softmax.
// ============================================================================
__device__ __forceinline__ void rescore_row(
    const uint32_t* u6, int n, int row, int c4, int* sidx3, float* swgt3)
{
    const float4* qp = (const float4*)(g_Qf + ((size_t)n * TSEQ + row) * 128) + c4 * 8;
    float4 qv[8];
    #pragma unroll
    for (int p = 0; p < 8; p++) qv[p] = qp[p];
    int ids[6];
    #pragma unroll
    for (int j = 0; j < 6; j++) ids[j] = (int)(u6[j] & 2047u);
    float sc[6];
    #pragma unroll
    for (int j = 0; j < 6; j++) {
        const float4* kp = (const float4*)(g_Kf + ((size_t)n * TSEQ + ids[j]) * 128) + c4 * 8;
        float s = 0.f;
        #pragma unroll
        for (int p = 0; p < 8; p++) {
            float4 kv = kp[p];
            s += qv[p].x * kv.x + qv[p].y * kv.y + qv[p].z * kv.z + qv[p].w * kv.w;
        }
        s += __shfl_xor_sync(0xffffffffu, s, 1);
        s += __shfl_xor_sync(0xffffffffu, s, 2);
        sc[j] = s * SCL;
    }
    float b0 = -INFINITY, b1 = -INFINITY, b2 = -INFINITY;
    int i0 = 0, i1 = 0, i2 = 0;
    #pragma unroll
    for (int j = 0; j < 6; j++) INS3(sc[j], ids[j]);
    if (c4 == 0) {
        float e1 = expf(b1 - b0), e2 = expf(b2 - b0);
        float inv = 1.f / (1.f + e1 + e2);
        sidx3[0] = i0; sidx3[1] = i1; sidx3[2] = i2;
        swgt3[0] = inv; swgt3[1] = e1 * inv; swgt3[2] = e2 * inv;
    }
}

// ============================================================================
// Fused scores + top-k + attn@V + OUTPUT PROJECTION.
// Phase 1: pipelined bf16 HMMA scores with 2-way nt-interleaved chains +
//          gated top-4 per quad-lane.
// Phase 2: merges, exact fp32 rescore, attn scatter, OA -> smem (split bf16),
//          then per-CTA 3-term split-bf16 GEMM vs Wo (smem-resident).
// Smem reuse: OA tile overlays dead Q/K0; Wo overlays dead K1.
// ============================================================================
#define OFQ   0u
#define OFK0  34816u
#define OFK1  69632u
#define OFOA  0u           // phase 2 (overlays Q + K0)
#define OFWO  69632u       // phase 2 (overlays K1)
#define OFU6  137216       // 128 rows x 6 u32 = 3072
#define OFSI  (137216 + 3072)
#define OFSW  (137216 + 3072 + 1536)
#define SMEMS (137216 + 3072 + 1536 + 1536)   // 143360

__global__ __launch_bounds__(512) void scores_fused(
    const float* __restrict__ E, float* __restrict__ attn,
    const float* __restrict__ bo, float* __restrict__ out)
{
    extern __shared__ __align__(16) char smc[];
    const int tid = threadIdx.x, lane = tid & 31, wid = tid >> 5;
    const int g = lane >> 2, c4 = lane & 3;
    const int half = wid >> 3, wq = wid & 7;
    const int n = blockIdx.y, m0 = blockIdx.x * 128;
    uint32_t* u6   = (uint32_t*)(smc + OFU6);
    int*      sidx = (int*)(smc + OFSI);
    float*    swgt = (float*)(smc + OFSW);

    // ---- load Q tile + K tile 0 ----
    {
        const uint4* gq = (const uint4*)(g_Qb + ((size_t)n * TSEQ + m0) * 128);
        const uint4* gk = (const uint4*)(g_Kb + ((size_t)n * TSEQ) * 128);
        #pragma unroll
        for (int j = 0; j < 4; j++) {
            int i = tid + j * 512;
            int r = i >> 4, c = i & 15;
            *(uint4*)(smc + OFQ  + r * 272 + c * 16) = gq[i];
            *(uint4*)(smc + OFK0 + r * 272 + c * 16) = gk[i];
        }
    }
    __syncthreads();

    // A fragments: rows wq*16.., 8 k-steps
    uint32_t A[8][4];
    {
        uint32_t ab = s2u(smc) + OFQ + (uint32_t)((wq * 16 + (lane & 15)) * 272 + (lane >> 4) * 16);
        #pragma unroll
        for (int ks = 0; ks < 8; ks++) LDMX4(A[ks], ab + ks * 32);
    }

    uint32_t cA0 = 0, cA1 = 0, cA2 = 0, cA3 = 0;
    uint32_t cB0 = 0, cB1 = 0, cB2 = 0, cB3 = 0;

    #pragma unroll 1
    for (int t = 0; t < 16; t++) {
        const uint32_t bufR = (t & 1) ? OFK1 : OFK0;
        const uint32_t bufW = (t & 1) ? OFK0 : OFK1;

        // stage next K tile from global (latency hidden behind MMAs below)
        uint4 st0, st1, st2, st3;
        if (t < 15) {
            const uint4* gk = (const uint4*)(g_Kb + ((size_t)n * TSEQ + (size_t)(t + 1) * 128) * 128);
            st0 = gk[tid]; st1 = gk[tid + 512]; st2 = gk[tid + 1024]; st3 = gk[tid + 1536];
        }

        // MMAs on current buffer: 4 pairs of interleaved nt chains (2-way ILP)
        #pragma unroll
        for (int p = 0; p < 4; p++) {
            const int ntg = half * 8 + p * 2;
            float c0 = 0.f, c1 = 0.f, c2 = 0.f, c3 = 0.f;
            float d0 = 0.f, d1 = 0.f, d2 = 0.f, d3 = 0.f;
            const char* br0 = smc + bufR + (ntg * 8 + g) * 272 + c4 * 4;
            const char* br1 = br0 + 8 * 272;
            #pragma unroll
            for (int ks = 0; ks < 8; ks++) {
                uint32_t b00 = *(const uint32_t*)(br0 + ks * 32);
                uint32_t b01 = *(const uint32_t*)(br0 + ks * 32 + 16);
                uint32_t b10 = *(const uint32_t*)(br1 + ks * 32);
                uint32_t b11 = *(const uint32_t*)(br1 + ks * 32 + 16);
                mma_bf16(c0, c1, c2, c3, A[ks][0], A[ks][1], A[ks][2], A[ks][3], b00, b01);
                mma_bf16(d0, d1, d2, d3, A[ks][0], A[ks][1], A[ks][2], A[ks][3], b10, b11);
            }
            uint32_t col = (uint32_t)(t * 128 + ntg * 8 + 2 * c4);
            UPD4(cA0, cA1, cA2, cA3, c0, col);
            UPD4(cA0, cA1, cA2, cA3, c1, col + 1);
            UPD4(cB0, cB1, cB2, cB3, c2, col);
            UPD4(cB0, cB1, cB2, cB3, c3, col + 1);
            UPD4(cA0, cA1, cA2, cA3, d0, col + 8);
            UPD4(cA0, cA1, cA2, cA3, d1, col + 9);
            UPD4(cB0, cB1, cB2, cB3, d2, col + 8);
            UPD4(cB0, cB1, cB2, cB3, d3, col + 9);
        }

        // commit staged tile to the other buffer
        if (t < 15) {
            int r0 = tid >> 4, c0i = tid & 15;
            *(uint4*)(smc + bufW + r0 * 272 + c0i * 16) = st0;
            int i1 = tid + 512;  *(uint4*)(smc + bufW + (i1 >> 4) * 272 + (i1 & 15) * 16) = st1;
            int i2 = tid + 1024; *(uint4*)(smc + bufW + (i2 >> 4) * 272 + (i2 & 15) * 16) = st2;
            int i3 = tid + 1536; *(uint4*)(smc + bufW + (i3 >> 4) * 272 + (i3 & 15) * 16) = st3;
        }
        __syncthreads();
    }

    // ---- quad merge (cols within half) ----
    uint32_t uA0 = cA0, uA1 = cA1, uA2 = cA2, uA3 = cA3, uA4 = 0, uA5 = 0;
    uint32_t uB0 = cB0, uB1 = cB1, uB2 = cB2, uB3 = cB3, uB4 = 0, uB5 = 0;
    #pragma unroll
    for (int mk = 1; mk <= 2; mk <<= 1) {
        uint32_t o0 = __shfl_xor_sync(0xffffffffu, uA0, mk);
        uint32_t o1 = __shfl_xor_sync(0xffffffffu, uA1, mk);
        uint32_t o2 = __shfl_xor_sync(0xffffffffu, uA2, mk);
        uint32_t o3 = __shfl_xor_sync(0xffffffffu, uA3, mk);
        uint32_t o4 = __shfl_xor_sync(0xffffffffu, uA4, mk);
        uint32_t o5 = __shfl_xor_sync(0xffffffffu, uA5, mk);
        INS6(uA0, uA1, uA2, uA3, uA4, uA5, o0); INS6(uA0, uA1, uA2, uA3, uA4, uA5, o1);
        INS6(uA0, uA1, uA2, uA3, uA4, uA5, o2); INS6(uA0, uA1, uA2, uA3, uA4, uA5, o3);
        INS6(uA0, uA1, uA2, uA3, uA4, uA5, o4); INS6(uA0, uA1, uA2, uA3, uA4, uA5, o5);
        o0 = __shfl_xor_sync(0xffffffffu, uB0, mk);
        o1 = __shfl_xor_sync(0xffffffffu, uB1, mk);
        o2 = __shfl_xor_sync(0xffffffffu, uB2, mk);
        o3 = __shfl_xor_sync(0xffffffffu, uB3, mk);
        o4 = __shfl_xor_sync(0xffffffffu, uB4, mk);
        o5 = __shfl_xor_sync(0xffffffffu, uB5, mk);
        INS6(uB0, uB1, uB2, uB3, uB4, uB5, o0); INS6(uB0, uB1, uB2, uB3, uB4, uB5, o1);
        INS6(uB0, uB1, uB2, uB3, uB4, uB5, o2); INS6(uB0, uB1, uB2, uB3, uB4, uB5, o3);
        INS6(uB0, uB1, uB2, uB3, uB4, uB5, o4); INS6(uB0, uB1, uB2, uB3, uB4, uB5, o5);
    }

    const int rowA = wq * 16 + g, rowB = rowA + 8;
    // cross-half merge via smem
    if (half == 1 && c4 == 0) {
        u6[rowA * 6 + 0] = uA0; u6[rowA * 6 + 1] = uA1; u6[rowA * 6 + 2] = uA2;
        u6[rowA * 6 + 3] = uA3; u6[rowA * 6 + 4] = uA4; u6[rowA * 6 + 5] = uA5;
        u6[rowB * 6 + 0] = uB0; u6[rowB * 6 + 1] = uB1; u6[rowB * 6 + 2] = uB2;
        u6[rowB * 6 + 3] = uB3; u6[rowB * 6 + 4] = uB4; u6[rowB * 6 + 5] = uB5;
    }
    __syncthreads();
    if (half == 0) {
        #pragma unroll
        for (int j = 0; j < 6; j++) { INS6(uA0, uA1, uA2, uA3, uA4, uA5, u6[rowA * 6 + j]); }
        #pragma unroll
        for (int j = 0; j < 6; j++) { INS6(uB0, uB1, uB2, uB3, uB4, uB5, u6[rowB * 6 + j]); }
    }
    __syncthreads();
    if (half == 0 && c4 == 0) {
        u6[rowA * 6 + 0] = uA0; u6[rowA * 6 + 1] = uA1; u6[rowA * 6 + 2] = uA2;
        u6[rowA * 6 + 3] = uA3; u6[rowA * 6 + 4] = uA4; u6[rowA * 6 + 5] = uA5;
        u6[rowB * 6 + 0] = uB0; u6[rowB * 6 + 1] = uB1; u6[rowB * 6 + 2] = uB2;
        u6[rowB * 6 + 3] = uB3; u6[rowB * 6 + 4] = uB4; u6[rowB * 6 + 5] = uB5;
    }
    __syncthreads();

    // ---- load Wo split into smem (K buffers dead now) + exact rescore ----
    {
        const uint4* gw = (const uint4*)g_Wos;
        #pragma unroll
        for (int j = 0; j < 8; j++) {
            int i = tid + j * 512;
            int r = i >> 5, c = i & 31;
            *(uint4*)(smc + OFWO + r * 528 + c * 16) = gw[i];
        }
    }
    {
        const int row = wid * 8 + g;
        uint32_t cand[6];
        #pragma unroll
        for (int j = 0; j < 6; j++) cand[j] = u6[row * 6 + j];
        rescore_row(cand, n, m0 + row, c4, sidx + row * 3, swgt + row * 3);
    }
    __syncthreads();

    // scatter the 3 weights per row (zeros already written by proj_split)
    if (tid < 128) {
        float* arow = attn + ((size_t)n * TSEQ + m0 + tid) * TSEQ;
        arow[sidx[tid * 3 + 0]] = swgt[tid * 3 + 0];
        arow[sidx[tid * 3 + 1]] = swgt[tid * 3 + 1];
        arow[sidx[tid * 3 + 2]] = swgt[tid * 3 + 2];
    }

    // attn @ V (V = raw E) -> split-bf16 OA rows in SMEM (528-stride)
    for (int rr = wid; rr < 128; rr += 16) {
        int j0 = sidx[rr * 3], j1 = sidx[rr * 3 + 1], j2 = sidx[rr * 3 + 2];
        float w0 = swgt[rr * 3], w1 = swgt[rr * 3 + 1], w2 = swgt[rr * 3 + 2];
        float4 p0 = ((const float4*)(E + ((size_t)n * TSEQ + j0) * 128))[lane];
        float4 p1 = ((const float4*)(E + ((size_t)n * TSEQ + j1) * 128))[lane];
        float4 p2 = ((const float4*)(E + ((size_t)n * TSEQ + j2) * 128))[lane];
        float ox = w0 * p0.x + w1 * p1.x + w2 * p2.x;
        float oy = w0 * p0.y + w1 * p1.y + w2 * p2.y;
        float oz = w0 * p0.z + w1 * p1.z + w2 * p2.z;
        float ow = w0 * p0.w + w1 * p1.w + w2 * p2.w;
        __nv_bfloat16 hx = __float2bfloat16_rn(ox), hy = __float2bfloat16_rn(oy);
        __nv_bfloat16 hz = __float2bfloat16_rn(oz), hw = __float2bfloat16_rn(ow);
        __nv_bfloat162 h01, h23, l01, l23;
        h01.x = hx; h01.y = hy; h23.x = hz; h23.y = hw;
        l01.x = __float2bfloat16_rn(ox - __bfloat162float(hx));
        l01.y = __float2bfloat16_rn(oy - __bfloat162float(hy));
        l23.x = __float2bfloat16_rn(oz - __bfloat162float(hz));
        l23.y = __float2bfloat16_rn(ow - __bfloat162float(hw));
        char* orow = smc + OFOA + rr * 528;
        *(__nv_bfloat162*)(orow + lane * 8)       = h01;
        *(__nv_bfloat162*)(orow + lane * 8 + 4)   = h23;
        *(__nv_bfloat162*)(orow + 256 + lane * 8)     = l01;
        *(__nv_bfloat162*)(orow + 256 + lane * 8 + 4) = l23;
    }
    __syncthreads();

    // ---- fused output projection: out_tile = OA @ Wo^T + bo ----
    {
        const int wg = wid & 7, hf = wid >> 3;   // row-group / nt-half
        uint32_t Ag[16][4];
        uint32_t ab2 = s2u(smc) + OFOA + (uint32_t)((wg * 16 + (lane & 15)) * 528 + (lane >> 4) * 16);
        #pragma unroll
        for (int ks = 0; ks < 16; ks++) LDMX4(Ag[ks], ab2 + ks * 32);

        #pragma unroll
        for (int ntg = 0; ntg < 2; ntg++) {
            float acc[4][4];
            #pragma unroll
            for (int j = 0; j < 4; j++)
                #pragma unroll
                for (int q = 0; q < 4; q++) acc[j][q] = 0.f;

            #pragma unroll
            for (int ks = 0; ks < 8; ks++) {
                #pragma unroll
                for (int j = 0; j < 4; j++) {
                    const char* br = smc + OFWO + ((hf * 8 + ntg * 4 + j) * 8 + g) * 528 + c4 * 4;
                    uint32_t b0 = *(const uint32_t*)(br + ks * 32);
                    uint32_t b1 = *(const uint32_t*)(br + ks * 32 + 16);
                    mma_bf16(acc[j][0], acc[j][1], acc[j][2], acc[j][3],
                             Ag[ks][0], Ag[ks][1], Ag[ks][2], Ag[ks][3], b0, b1);
                    mma_bf16(acc[j][0], acc[j][1], acc[j][2], acc[j][3],
                             Ag[8 + ks][0], Ag[8 + ks][1], Ag[8 + ks][2], Ag[8 + ks][3], b0, b1);
                    uint32_t l0 = *(const uint32_t*)(br + 256 + ks * 32);
                    uint32_t l1 = *(const uint32_t*)(br + 256 + ks * 32 + 16);
                    mma_bf16(acc[j][0], acc[j][1], acc[j][2], acc[j][3],
                             Ag[ks][0], Ag[ks][1], Ag[ks][2], Ag[ks][3], l0, l1);
                }
            }

            #pragma unroll
            for (int j = 0; j < 4; j++) {
                const int nt = hf * 8 + ntg * 4 + j;
                const int rA = n * TSEQ + m0 + wg * 16 + g;
                const int col = nt * 8 + 2 * c4;
                float bb0 = bo[col], bb1 = bo[col + 1];
                *(float2*)(out + (size_t)rA * 128 + col)       = make_float2(acc[j][0] + bb0, acc[j][1] + bb1);
                *(float2*)(out + (size_t)(rA + 8) * 128 + col) = make_float2(acc[j][2] + bb0, acc[j][3] + bb1);
            }
        }
    }
}

// ============================================================================
extern "C" void kernel_launch(void* const* d_in, const int* in_sizes, int n_in,
                              void* d_out, int out_size)
{
    const float* E  = (const float*)d_in[0];
    const float* Wq = (const float*)d_in[2];
    const float* Wk = (const float*)d_in[3];
    const float* Wo = (const float*)d_in[4];
    const float* bo = (const float*)d_in[5];

    float* out  = (float*)d_out;                       // [8,2048,128]
    float* attn = out + (size_t)NBATCH * TSEQ * CDIM;  // [8,1,2048,2048]

    const int SMEM_G = 128 * 128 * 2 * sizeof(float);  // 131072 (proj)
    cudaFuncSetAttribute(proj_split,   cudaFuncAttributeMaxDynamicSharedMemorySize, SMEM_G);
    cudaFuncSetAttribute(scores_fused, cudaFuncAttributeMaxDynamicSharedMemorySize, SMEMS);

    prep_wo<<<16, 256>>>((const float4*)Wo);
    proj_split<<<dim3(128, 2), 256, SMEM_G>>>(E, Wq, Wk, attn);
    scores_fused<<<dim3(16, NBATCH), 512, SMEMS>>>(E, attn, bo, out);
}

// round 16
// speedup vs baseline: 1.1276x; 1.0154x over previous
#include <cuda_runtime.h>
#include <cuda_bf16.h>
#include <math.h>
#include <stdint.h>

#define NBATCH 8
#define TSEQ   2048
#define CDIM   128
#define SCL    0.08838834764831845f   // 1/sqrt(128)

// -------- scratch (static __device__ per harness rules) --------
__device__ float         g_Qf [(size_t)NBATCH * TSEQ * CDIM]; // fp32 Q (raw)
__device__ float         g_Kf [(size_t)NBATCH * TSEQ * CDIM]; // fp32 K (raw)
__device__ __nv_bfloat16 g_Qb [(size_t)NBATCH * TSEQ * CDIM]; // bf16 Q (pre-scaled)
__device__ __nv_bfloat16 g_Kb [(size_t)NBATCH * TSEQ * CDIM]; // bf16 K
__device__ __nv_bfloat16 g_Wos[128 * 256];                    // Wo split [hi||lo]

__device__ __forceinline__ uint32_t s2u(const void* p) {
    uint32_t a;
    asm("{ .reg .u64 t; cvta.to.shared.u64 t, %1; cvt.u32.u64 %0, t; }" : "=r"(a) : "l"(p));
    return a;
}
__device__ __forceinline__ uint32_t umx(uint32_t a, uint32_t b) { return a > b ? a : b; }
__device__ __forceinline__ uint32_t umn(uint32_t a, uint32_t b) { return a < b ? a : b; }

__device__ __forceinline__ void mma_bf16(float& c0, float& c1, float& c2, float& c3,
    uint32_t a0, uint32_t a1, uint32_t a2, uint32_t a3, uint32_t b0, uint32_t b1) {
    asm volatile("mma.sync.aligned.m16n8k16.row.col.f32.bf16.bf16.f32 "
        "{%0,%1,%2,%3}, {%4,%5,%6,%7}, {%8,%9}, {%0,%1,%2,%3};"
        : "+f"(c0), "+f"(c1), "+f"(c2), "+f"(c3)
        : "r"(a0), "r"(a1), "r"(a2), "r"(a3), "r"(b0), "r"(b1));
}
#define LDMX4(d, ad) \
    asm volatile("ldmatrix.sync.aligned.m8n8.x4.shared.b16 {%0,%1,%2,%3}, [%4];" \
        : "=r"((d)[0]), "=r"((d)[1]), "=r"((d)[2]), "=r"((d)[3]) : "r"(ad))

// gated packed top-4 chain update (R8 variant — measured best)
#define UPD4(r0, r1, r2, r3, f, cc) { \
    uint32_t mb = __float_as_uint(f); \
    mb = ((int)mb < 0) ? ~mb : (mb | 0x80000000u); \
    uint32_t x = (mb & 0xFFFFF800u) | (cc); \
    if (x > r3) { uint32_t tt; \
        tt = umx(r0, x); x = umn(r0, x); r0 = tt; \
        tt = umx(r1, x); x = umn(r1, x); r1 = tt; \
        tt = umx(r2, x); x = umn(r2, x); r2 = tt; \
        r3 = umx(r3, x); } }

#define INS6(r0, r1, r2, r3, r4, r5, xx) { uint32_t y = (xx), tt; \
    tt = umx(r0, y); y = umn(r0, y); r0 = tt; \
    tt = umx(r1, y); y = umn(r1, y); r1 = tt; \
    tt = umx(r2, y); y = umn(r2, y); r2 = tt; \
    tt = umx(r3, y); y = umn(r3, y); r3 = tt; \
    tt = umx(r4, y); y = umn(r4, y); r4 = tt; \
    r5 = umx(r5, y); }

#define INS3(vv, cc) do { float _v = (vv); int _c = (cc); \
    if (_v > b2) { \
        if (_v > b1) { \
            if (_v > b0) { b2 = b1; i2 = i1; b1 = b0; i1 = i0; b0 = _v; i0 = _c; } \
            else         { b2 = b1; i2 = i1; b1 = _v; i1 = _c; } \
        } else           { b2 = _v; i2 = _c; } \
    } } while (0)

// ============================================================================
// Q/K projection (SIMT fp32, exact) + attention zero-fill + Wo-split prep.
// ============================================================================
__global__ __launch_bounds__(256) void proj_split(
    const float* __restrict__ E, const float* __restrict__ Wq, const float* __restrict__ Wk,
    float* __restrict__ attn, const float4* __restrict__ Wo)
{
    extern __shared__ float smf[];
    float* As = smf;
    float* Bs = smf + 128 * 128;
    const int tid = threadIdx.x, tx = tid & 15, ty = tid >> 4;
    const int m0 = blockIdx.x * 128;
    const int isK = blockIdx.y;
    const float* W = isK ? Wk : Wq;
    float*         df = isK ? g_Kf : g_Qf;
    __nv_bfloat16* db = isK ? g_Kb : g_Qb;
    const float bscale = isK ? 1.f : SCL;

    // ---- fold in Wo hi/lo split (first 16 CTAs of the Q slice) ----
    if (isK == 0 && blockIdx.x < 16) {
        int local = blockIdx.x * 256 + tid;
        float4 v = Wo[local];
        int row = local >> 5, c4b = (local & 31) * 4;
        __nv_bfloat16 h0 = __float2bfloat16_rn(v.x), h1 = __float2bfloat16_rn(v.y);
        __nv_bfloat16 h2 = __float2bfloat16_rn(v.z), h3 = __float2bfloat16_rn(v.w);
        __nv_bfloat162 hp0, hp1, lp0, lp1;
        hp0.x = h0; hp0.y = h1; hp1.x = h2; hp1.y = h3;
        lp0.x = __float2bfloat16_rn(v.x - __bfloat162float(h0));
        lp0.y = __float2bfloat16_rn(v.y - __bfloat162float(h1));
        lp1.x = __float2bfloat16_rn(v.z - __bfloat162float(h2));
        lp1.y = __float2bfloat16_rn(v.w - __bfloat162float(h3));
        __nv_bfloat162* ph = (__nv_bfloat162*)(g_Wos + (size_t)row * 256 + c4b);
        ph[0] = hp0; ph[1] = hp1;
        __nv_bfloat162* pl = (__nv_bfloat162*)(g_Wos + (size_t)row * 256 + 128 + c4b);
        pl[0] = lp0; pl[1] = lp1;
    }

    {
        const float4* src = (const float4*)(E + (size_t)m0 * 128);
        #pragma unroll
        for (int i = tid; i < 128 * 32; i += 256) {
            int r = i & 127, cq = i >> 7;
            float4 v = src[(size_t)r * 32 + cq];
            float* d = As + (cq * 4) * 128 + r;
            d[0] = v.x; d[128] = v.y; d[256] = v.z; d[384] = v.w;
        }
        const float4* srcb = (const float4*)W;
        #pragma unroll
        for (int i = tid; i < 128 * 32; i += 256) {
            int r = i & 127, cq = i >> 7;
            float4 v = srcb[(size_t)r * 32 + cq];
            float* d = Bs + (cq * 4) * 128 + r;
            d[0] = v.x; d[128] = v.y; d[256] = v.z; d[384] = v.w;
        }
    }

    // ---- attention zero-fill: this CTA covers 1/256 of attn (2 MB) ----
    {
        const int cid = blockIdx.y * 128 + blockIdx.x;
        uint4* az = (uint4*)attn + (size_t)cid * 32768 + tid;
        uint4 zz = make_uint4(0, 0, 0, 0);
        #pragma unroll 8
        for (int j = 0; j < 128; j++) az[j * 256] = zz;
    }
    __syncthreads();

    float acc[8][8];
    #pragma unroll
    for (int i = 0; i < 8; i++)
        #pragma unroll
        for (int j = 0; j < 8; j++) acc[i][j] = 0.f;

    #pragma unroll 4
    for (int c = 0; c < 128; c++) {
        const float* ac = As + c * 128;
        const float* bc = Bs + c * 128;
        float4 a0 = *(const float4*)(ac + ty * 4);
        float4 a1 = *(const float4*)(ac + 64 + ty * 4);
        float4 b0 = *(const float4*)(bc + tx * 4);
        float4 b1 = *(const float4*)(bc + 64 + tx * 4);
        float a[8] = {a0.x, a0.y, a0.z, a0.w, a1.x, a1.y, a1.z, a1.w};
        float b[8] = {b0.x, b0.y, b0.z, b0.w, b1.x, b1.y, b1.z, b1.w};
        #pragma unroll
        for (int i = 0; i < 8; i++)
            #pragma unroll
            for (int j = 0; j < 8; j++)
                acc[i][j] += a[i] * b[j];
    }

    #pragma unroll
    for (int ih = 0; ih < 2; ih++) {
        #pragma unroll
        for (int i = 0; i < 4; i++) {
            const int row = m0 + ih * 64 + ty * 4 + i;
            #pragma unroll
            for (int jh = 0; jh < 2; jh++) {
                const int col = jh * 64 + tx * 4;
                float a0 = acc[ih * 4 + i][jh * 4 + 0];
                float a1 = acc[ih * 4 + i][jh * 4 + 1];
                float a2 = acc[ih * 4 + i][jh * 4 + 2];
                float a3 = acc[ih * 4 + i][jh * 4 + 3];
                *(float4*)(df + (size_t)row * 128 + col) = make_float4(a0, a1, a2, a3);
                __nv_bfloat162 p01, p23;
                p01.x = __float2bfloat16_rn(a0 * bscale);
                p01.y = __float2bfloat16_rn(a1 * bscale);
                p23.x = __float2bfloat16_rn(a2 * bscale);
                p23.y = __float2bfloat16_rn(a3 * bscale);
                __nv_bfloat162* pb = (__nv_bfloat162*)(db + (size_t)row * 128 + col);
                pb[0] = p01; pb[1] = p23;
            }
        }
    }
}

// ============================================================================
// Exact rescore of 6 candidates for one row (quad-cooperative), top-3+softmax.
// ============================================================================
__device__ __forceinline__ void rescore_row(
    const uint32_t* u6, int n, int row, int c4, int* sidx3, float* swgt3)
{
    const float4* qp = (const float4*)(g_Qf + ((size_t)n * TSEQ + row) * 128) + c4 * 8;
    float4 qv[8];
    #pragma unroll
    for (int p = 0; p < 8; p++) qv[p] = qp[p];
    int ids[6];
    #pragma unroll
    for (int j = 0; j < 6; j++) ids[j] = (int)(u6[j] & 2047u);
    float sc[6];
    #pragma unroll
    for (int j = 0; j < 6; j++) {
        const float4* kp = (const float4*)(g_Kf + ((size_t)n * TSEQ + ids[j]) * 128) + c4 * 8;
        float s = 0.f;
        #pragma unroll
        for (int p = 0; p < 8; p++) {
            float4 kv = kp[p];
            s += qv[p].x * kv.x + qv[p].y * kv.y + qv[p].z * kv.z + qv[p].w * kv.w;
        }
        s += __shfl_xor_sync(0xffffffffu, s, 1);
        s += __shfl_xor_sync(0xffffffffu, s, 2);
        sc[j] = s * SCL;
    }
    float b0 = -INFINITY, b1 = -INFINITY, b2 = -INFINITY;
    int i0 = 0, i1 = 0, i2 = 0;
    #pragma unroll
    for (int j = 0; j < 6; j++) INS3(sc[j], ids[j]);
    if (c4 == 0) {
        float e1 = expf(b1 - b0), e2 = expf(b2 - b0);
        float inv = 1.f / (1.f + e1 + e2);
        sidx3[0] = i0; sidx3[1] = i1; sidx3[2] = i2;
        swgt3[0] = inv; swgt3[1] = e1 * inv; swgt3[2] = e2 * inv;
    }
}

// ============================================================================
// Fused scores + top-k + attn@V + output projection.
// Scores inner loop: 2 groups x 4 INDEPENDENT nt chains (4-way MMA ILP).
// ============================================================================
#define OFQ   0u
#define OFK0  34816u
#define OFK1  69632u
#define OFOA  0u           // phase 2 (overlays Q + K0)
#define OFWO  69632u       // phase 2 (overlays K1)
#define OFU6  137216       // 128 rows x 6 u32 = 3072
#define OFSI  (137216 + 3072)
#define OFSW  (137216 + 3072 + 1536)
#define SMEMS (137216 + 3072 + 1536 + 1536)   // 143360

__global__ __launch_bounds__(512) void scores_fused(
    const float* __restrict__ E, float* __restrict__ attn,
    const float* __restrict__ bo, float* __restrict__ out)
{
    extern __shared__ __align__(16) char smc[];
    const int tid = threadIdx.x, lane = tid & 31, wid = tid >> 5;
    const int g = lane >> 2, c4 = lane & 3;
    const int half = wid >> 3, wq = wid & 7;
    const int n = blockIdx.y, m0 = blockIdx.x * 128;
    uint32_t* u6   = (uint32_t*)(smc + OFU6);
    int*      sidx = (int*)(smc + OFSI);
    float*    swgt = (float*)(smc + OFSW);

    // ---- load Q tile + K tile 0 ----
    {
        const uint4* gq = (const uint4*)(g_Qb + ((size_t)n * TSEQ + m0) * 128);
        const uint4* gk = (const uint4*)(g_Kb + ((size_t)n * TSEQ) * 128);
        #pragma unroll
        for (int j = 0; j < 4; j++) {
            int i = tid + j * 512;
            int r = i >> 4, c = i & 15;
            *(uint4*)(smc + OFQ  + r * 272 + c * 16) = gq[i];
            *(uint4*)(smc + OFK0 + r * 272 + c * 16) = gk[i];
        }
    }
    __syncthreads();

    // A fragments: rows wq*16.., 8 k-steps
    uint32_t A[8][4];
    {
        uint32_t ab = s2u(smc) + OFQ + (uint32_t)((wq * 16 + (lane & 15)) * 272 + (lane >> 4) * 16);
        #pragma unroll
        for (int ks = 0; ks < 8; ks++) LDMX4(A[ks], ab + ks * 32);
    }

    uint32_t cA0 = 0, cA1 = 0, cA2 = 0, cA3 = 0;
    uint32_t cB0 = 0, cB1 = 0, cB2 = 0, cB3 = 0;

    #pragma unroll 1
    for (int t = 0; t < 16; t++) {
        const uint32_t bufR = (t & 1) ? OFK1 : OFK0;
        const uint32_t bufW = (t & 1) ? OFK0 : OFK1;

        // stage next K tile from global (latency hidden behind MMAs below)
        uint4 st0, st1, st2, st3;
        if (t < 15) {
            const uint4* gk = (const uint4*)(g_Kb + ((size_t)n * TSEQ + (size_t)(t + 1) * 128) * 128);
            st0 = gk[tid]; st1 = gk[tid + 512]; st2 = gk[tid + 1024]; st3 = gk[tid + 1536];
        }

        // MMAs: 2 groups of 4 independent nt chains (4-way ILP)
        #pragma unroll
        for (int p = 0; p < 2; p++) {
            const int ntg = half * 8 + p * 4;
            float ac[4][4];
            #pragma unroll
            for (int j = 0; j < 4; j++)
                #pragma unroll
                for (int q = 0; q < 4; q++) ac[j][q] = 0.f;

            const char* br = smc + bufR + (ntg * 8 + g) * 272 + c4 * 4;
            #pragma unroll
            for (int ks = 0; ks < 8; ks++) {
                #pragma unroll
                for (int j = 0; j < 4; j++) {
                    const char* bj = br + j * (8 * 272) + ks * 32;
                    uint32_t b0 = *(const uint32_t*)(bj);
                    uint32_t b1 = *(const uint32_t*)(bj + 16);
                    mma_bf16(ac[j][0], ac[j][1], ac[j][2], ac[j][3],
                             A[ks][0], A[ks][1], A[ks][2], A[ks][3], b0, b1);
                }
            }
            #pragma unroll
            for (int j = 0; j < 4; j++) {
                uint32_t col = (uint32_t)(t * 128 + (ntg + j) * 8 + 2 * c4);
                UPD4(cA0, cA1, cA2, cA3, ac[j][0], col);
                UPD4(cA0, cA1, cA2, cA3, ac[j][1], col + 1);
                UPD4(cB0, cB1, cB2, cB3, ac[j][2], col);
                UPD4(cB0, cB1, cB2, cB3, ac[j][3], col + 1);
            }
        }

        // commit staged tile to the other buffer
        if (t < 15) {
            int r0 = tid >> 4, c0i = tid & 15;
            *(uint4*)(smc + bufW + r0 * 272 + c0i * 16) = st0;
            int i1 = tid + 512;  *(uint4*)(smc + bufW + (i1 >> 4) * 272 + (i1 & 15) * 16) = st1;
            int i2 = tid + 1024; *(uint4*)(smc + bufW + (i2 >> 4) * 272 + (i2 & 15) * 16) = st2;
            int i3 = tid + 1536; *(uint4*)(smc + bufW + (i3 >> 4) * 272 + (i3 & 15) * 16) = st3;
        }
        __syncthreads();
    }

    // ---- quad merge (cols within half) ----
    uint32_t uA0 = cA0, uA1 = cA1, uA2 = cA2, uA3 = cA3, uA4 = 0, uA5 = 0;
    uint32_t uB0 = cB0, uB1 = cB1, uB2 = cB2, uB3 = cB3, uB4 = 0, uB5 = 0;
    #pragma unroll
    for (int mk = 1; mk <= 2; mk <<= 1) {
        uint32_t o0 = __shfl_xor_sync(0xffffffffu, uA0, mk);
        uint32_t o1 = __shfl_xor_sync(0xffffffffu, uA1, mk);
        uint32_t o2 = __shfl_xor_sync(0xffffffffu, uA2, mk);
        uint32_t o3 = __shfl_xor_sync(0xffffffffu, uA3, mk);
        uint32_t o4 = __shfl_xor_sync(0xffffffffu, uA4, mk);
        uint32_t o5 = __shfl_xor_sync(0xffffffffu, uA5, mk);
        INS6(uA0, uA1, uA2, uA3, uA4, uA5, o0); INS6(uA0, uA1, uA2, uA3, uA4, uA5, o1);
        INS6(uA0, uA1, uA2, uA3, uA4, uA5, o2); INS6(uA0, uA1, uA2, uA3, uA4, uA5, o3);
        INS6(uA0, uA1, uA2, uA3, uA4, uA5, o4); INS6(uA0, uA1, uA2, uA3, uA4, uA5, o5);
        o0 = __shfl_xor_sync(0xffffffffu, uB0, mk);
        o1 = __shfl_xor_sync(0xffffffffu, uB1, mk);
        o2 = __shfl_xor_sync(0xffffffffu, uB2, mk);
        o3 = __shfl_xor_sync(0xffffffffu, uB3, mk);
        o4 = __shfl_xor_sync(0xffffffffu, uB4, mk);
        o5 = __shfl_xor_sync(0xffffffffu, uB5, mk);
        INS6(uB0, uB1, uB2, uB3, uB4, uB5, o0); INS6(uB0, uB1, uB2, uB3, uB4, uB5, o1);
        INS6(uB0, uB1, uB2, uB3, uB4, uB5, o2); INS6(uB0, uB1, uB2, uB3, uB4, uB5, o3);
        INS6(uB0, uB1, uB2, uB3, uB4, uB5, o4); INS6(uB0, uB1, uB2, uB3, uB4, uB5, o5);
    }

    const int rowA = wq * 16 + g, rowB = rowA + 8;
    // cross-half merge via smem
    if (half == 1 && c4 == 0) {
        u6[rowA * 6 + 0] = uA0; u6[rowA * 6 + 1] = uA1; u6[rowA * 6 + 2] = uA2;
        u6[rowA * 6 + 3] = uA3; u6[rowA * 6 + 4] = uA4; u6[rowA * 6 + 5] = uA5;
        u6[rowB * 6 + 0] = uB0; u6[rowB * 6 + 1] = uB1; u6[rowB * 6 + 2] = uB2;
        u6[rowB * 6 + 3] = uB3; u6[rowB * 6 + 4] = uB4; u6[rowB * 6 + 5] = uB5;
    }
    __syncthreads();
    if (half == 0) {
        #pragma unroll
        for (int j = 0; j < 6; j++) { INS6(uA0, uA1, uA2, uA3, uA4, uA5, u6[rowA * 6 + j]); }
        #pragma unroll
        for (int j = 0; j < 6; j++) { INS6(uB0, uB1, uB2, uB3, uB4, uB5, u6[rowB * 6 + j]); }
    }
    __syncthreads();
    if (half == 0 && c4 == 0) {
        u6[rowA * 6 + 0] = uA0; u6[rowA * 6 + 1] = uA1; u6[rowA * 6 + 2] = uA2;
        u6[rowA * 6 + 3] = uA3; u6[rowA * 6 + 4] = uA4; u6[rowA * 6 + 5] = uA5;
        u6[rowB * 6 + 0] = uB0; u6[rowB * 6 + 1] = uB1; u6[rowB * 6 + 2] = uB2;
        u6[rowB * 6 + 3] = uB3; u6[rowB * 6 + 4] = uB4; u6[rowB * 6 + 5] = uB5;
    }
    __syncthreads();

    // ---- load Wo split into smem (K buffers dead now) + exact rescore ----
    {
        const uint4* gw = (const uint4*)g_Wos;
        #pragma unroll
        for (int j = 0; j < 8; j++) {
            int i = tid + j * 512;
            int r = i >> 5, c = i & 31;
            *(uint4*)(smc + OFWO + r * 528 + c * 16) = gw[i];
        }
    }
    {
        const int row = wid * 8 + g;
        uint32_t cand[6];
        #pragma unroll
        for (int j = 0; j < 6; j++) cand[j] = u6[row * 6 + j];
        rescore_row(cand, n, m0 + row, c4, sidx + row * 3, swgt + row * 3);
    }
    __syncthreads();

    // scatter the 3 weights per row (zeros already written by proj_split)
    if (tid < 128) {
        float* arow = attn + ((size_t)n * TSEQ + m0 + tid) * TSEQ;
        arow[sidx[tid * 3 + 0]] = swgt[tid * 3 + 0];
        arow[sidx[tid * 3 + 1]] = swgt[tid * 3 + 1];
        arow[sidx[tid * 3 + 2]] = swgt[tid * 3 + 2];
    }

    // attn @ V (V = raw E) -> split-bf16 OA rows in SMEM (528-stride)
    for (int rr = wid; rr < 128; rr += 16) {
        int j0 = sidx[rr * 3], j1 = sidx[rr * 3 + 1], j2 = sidx[rr * 3 + 2];
        float w0 = swgt[rr * 3], w1 = swgt[rr * 3 + 1], w2 = swgt[rr * 3 + 2];
        float4 p0 = ((const float4*)(E + ((size_t)n * TSEQ + j0) * 128))[lane];
        float4 p1 = ((const float4*)(E + ((size_t)n * TSEQ + j1) * 128))[lane];
        float4 p2 = ((const float4*)(E + ((size_t)n * TSEQ + j2) * 128))[lane];
        float ox = w0 * p0.x + w1 * p1.x + w2 * p2.x;
        float oy = w0 * p0.y + w1 * p1.y + w2 * p2.y;
        float oz = w0 * p0.z + w1 * p1.z + w2 * p2.z;
        float ow = w0 * p0.w + w1 * p1.w + w2 * p2.w;
        __nv_bfloat16 hx = __float2bfloat16_rn(ox), hy = __float2bfloat16_rn(oy);
        __nv_bfloat16 hz = __float2bfloat16_rn(oz), hw = __float2bfloat16_rn(ow);
        __nv_bfloat162 h01, h23, l01, l23;
        h01.x = hx; h01.y = hy; h23.x = hz; h23.y = hw;
        l01.x = __float2bfloat16_rn(ox - __bfloat162float(hx));
        l01.y = __float2bfloat16_rn(oy - __bfloat162float(hy));
        l23.x = __float2bfloat16_rn(oz - __bfloat162float(hz));
        l23.y = __float2bfloat16_rn(ow - __bfloat162float(hw));
        char* orow = smc + OFOA + rr * 528;
        *(__nv_bfloat162*)(orow + lane * 8)       = h01;
        *(__nv_bfloat162*)(orow + lane * 8 + 4)   = h23;
        *(__nv_bfloat162*)(orow + 256 + lane * 8)     = l01;
        *(__nv_bfloat162*)(orow + 256 + lane * 8 + 4) = l23;
    }
    __syncthreads();

    // ---- fused output projection: out_tile = OA @ Wo^T + bo ----
    {
        const int wg = wid & 7, hf = wid >> 3;   // row-group / nt-half
        uint32_t Ag[16][4];
        uint32_t ab2 = s2u(smc) + OFOA + (uint32_t)((wg * 16 + (lane & 15)) * 528 + (lane >> 4) * 16);
        #pragma unroll
        for (int ks = 0; ks < 16; ks++) LDMX4(Ag[ks], ab2 + ks * 32);

        #pragma unroll
        for (int ntg = 0; ntg < 2; ntg++) {
            float acc[4][4];
            #pragma unroll
            for (int j = 0; j < 4; j++)
                #pragma unroll
                for (int q = 0; q < 4; q++) acc[j][q] = 0.f;

            #pragma unroll
            for (int ks = 0; ks < 8; ks++) {
                #pragma unroll
                for (int j = 0; j < 4; j++) {
                    const char* br = smc + OFWO + ((hf * 8 + ntg * 4 + j) * 8 + g) * 528 + c4 * 4;
                    uint32_t b0 = *(const uint32_t*)(br + ks * 32);
                    uint32_t b1 = *(const uint32_t*)(br + ks * 32 + 16);
                    mma_bf16(acc[j][0], acc[j][1], acc[j][2], acc[j][3],
                             Ag[ks][0], Ag[ks][1], Ag[ks][2], Ag[ks][3], b0, b1);
                    mma_bf16(acc[j][0], acc[j][1], acc[j][2], acc[j][3],
                             Ag[8 + ks][0], Ag[8 + ks][1], Ag[8 + ks][2], Ag[8 + ks][3], b0, b1);
                    uint32_t l0 = *(const uint32_t*)(br + 256 + ks * 32);
                    uint32_t l1 = *(const uint32_t*)(br + 256 + ks * 32 + 16);
                    mma_bf16(acc[j][0], acc[j][1], acc[j][2], acc[j][3],
                             Ag[ks][0], Ag[ks][1], Ag[ks][2], Ag[ks][3], l0, l1);
                }
            }

            #pragma unroll
            for (int j = 0; j < 4; j++) {
                const int nt = hf * 8 + ntg * 4 + j;
                const int rA = n * TSEQ + m0 + wg * 16 + g;
                const int col = nt * 8 + 2 * c4;
                float bb0 = bo[col], bb1 = bo[col + 1];
                *(float2*)(out + (size_t)rA * 128 + col)       = make_float2(acc[j][0] + bb0, acc[j][1] + bb1);
                *(float2*)(out + (size_t)(rA + 8) * 128 + col) = make_float2(acc[j][2] + bb0, acc[j][3] + bb1);
            }
        }
    }
}

// ============================================================================
extern "C" void kernel_launch(void* const* d_in, const int* in_sizes, int n_in,
                              void* d_out, int out_size)
{
    const float* E  = (const float*)d_in[0];
    const float* Wq = (const float*)d_in[2];
    const float* Wk = (const float*)d_in[3];
    const float* Wo = (const float*)d_in[4];
    const float* bo = (const float*)d_in[5];

    float* out  = (float*)d_out;                       // [8,2048,128]
    float* attn = out + (size_t)NBATCH * TSEQ * CDIM;  // [8,1,2048,2048]

    const int SMEM_G = 128 * 128 * 2 * sizeof(float);  // 131072 (proj)
    cudaFuncSetAttribute(proj_split,   cudaFuncAttributeMaxDynamicSharedMemorySize, SMEM_G);
    cudaFuncSetAttribute(scores_fused, cudaFuncAttributeMaxDynamicSharedMemorySize, SMEMS);

    proj_split<<<dim3(128, 2), 256, SMEM_G>>>(E, Wq, Wk, attn, (const float4*)Wo);
    scores_fused<<<dim3(16, NBATCH), 512, SMEMS>>>(E, attn, bo, out);
}